// round 10
// baseline (speedup 1.0000x reference)
#include <cuda_runtime.h>
#include <math.h>
#include <stdint.h>

#define NB 4
#define C2C 128
#define HH 128
#define WW 128
#define PP (HH*WW)          // 16384
#define GKC 40

#define BK 32
#define AS_STRIDE 36
#define KSTAGES 3
#define MAX_STAGE_WORDS 13568
#define GSMEM_WORDS (KSTAGES*MAX_STAGE_WORDS + 384)
#define GSMEM_BYTES (GSMEM_WORDS*4)       // 164352

// conv-GEMM (128x256 tile, 2-stage register-staged)
#define CV_BM 128
#define CV_BN 256
#define CV_BSTR 264
#define CV_AW (CV_BM*AS_STRIDE)           // 4608
#define CV_BW (BK*CV_BSTR)                // 8448
#define CV_STAGE (CV_AW+CV_BW)            // 13056
#define CVSMEM_BYTES (2*CV_STAGE*4)       // 104448

// ---------------- scratch -----------------------------------------------------
__device__ float g_h[(size_t)NB*256*PP];
__device__ float g_mid[(size_t)NB*64*PP];
__device__ float g_xconv[(size_t)NB*C2C*PP];
__device__ float g_k[(size_t)NB*GKC*PP];
__device__ float g_attnh[(size_t)NB*C2C*PP];
__device__ float g_attn[(size_t)NB*C2C*PP];
__device__ float g_atmean[NB*C2C];
__device__ float g_xcmean[NB*PP];
__device__ float g_ssig[NB*PP];
__device__ float g_csig[NB*C2C];

// ---------------- tf32 / cp.async helpers --------------------------------------
__device__ __forceinline__ uint32_t f2tf32(float x) {
    uint32_t u;
    asm("cvt.rna.tf32.f32 %0, %1;" : "=r"(u) : "f"(x));
    return u;
}
__device__ __forceinline__ void mma_tf32(float c[4], const uint32_t a[4], const uint32_t b[2]) {
    asm volatile(
        "mma.sync.aligned.m16n8k8.row.col.f32.tf32.tf32.f32 "
        "{%0,%1,%2,%3}, {%4,%5,%6,%7}, {%8,%9}, {%0,%1,%2,%3};\n"
        : "+f"(c[0]), "+f"(c[1]), "+f"(c[2]), "+f"(c[3])
        : "r"(a[0]), "r"(a[1]), "r"(a[2]), "r"(a[3]), "r"(b[0]), "r"(b[1]));
}
__device__ __forceinline__ void cp16(uint32_t dst, const void* src) {
    asm volatile("cp.async.cg.shared.global [%0], [%1], 16;\n"
                 :: "r"(dst), "l"(src) : "memory");
}
__device__ __forceinline__ void cp16_sz(uint32_t dst, const void* src, int sz) {
    asm volatile("cp.async.cg.shared.global [%0], [%1], 16, %2;\n"
                 :: "r"(dst), "l"(src), "r"(sz) : "memory");
}
__device__ __forceinline__ void cp_commit() {
    asm volatile("cp.async.commit_group;\n" ::: "memory");
}

// ---------------- window loader (horizontal, 10 taps around w4) ---------------
__device__ __forceinline__ void load_win10(const float* __restrict__ xr, int w4, float v[10]) {
    if (w4 >= 4 && w4 + 8 <= WW) {
        float4 A = *(const float4*)(xr + w4 - 4);
        float4 Bv = *(const float4*)(xr + w4);
        float4 Cv = *(const float4*)(xr + w4 + 4);
        v[0] = A.y;  v[1] = A.z;  v[2] = A.w;
        v[3] = Bv.x; v[4] = Bv.y; v[5] = Bv.z; v[6] = Bv.w;
        v[7] = Cv.x; v[8] = Cv.y; v[9] = Cv.z;
    } else {
#pragma unroll
        for (int t = 0; t < 10; t++) {
            int wi = w4 - 3 + t;
            v[t] = (wi >= 0 && wi < WW) ? xr[wi] : 0.f;
        }
    }
}

// ---------------- tf32 GEMM v6 (unchanged from R9 best) ------------------------
template<int ACT, int GATE, int WM>
__global__ __launch_bounds__(512) void gemm_tc(
    const float* __restrict__ A, const float* __restrict__ bias,
    const float* __restrict__ Bm, float* __restrict__ Cm,
    int M, int K, int N, size_t sB, size_t sC,
    const float* __restrict__ gAtt, const float* __restrict__ gSs,
    const float* __restrict__ gCs)
{
    constexpr int WN = 16 / WM;
    constexpr int TBM = WM * 32;
    constexpr int TBN = WN * 64;
    constexpr int BS_STRIDE = TBN + 8;
    constexpr int A_WORDS = TBM * AS_STRIDE;
    constexpr int B_WORDS = BK * BS_STRIDE;
    constexpr int STAGE_WORDS = A_WORDS + B_WORDS;
    constexpr int A_PASSES = TBM / 64;
    constexpr int B_PASSES = TBN / 64;
    constexpr int B_ROWS_PER_PASS = 2048 / TBN;

    extern __shared__ float sm[];
    float* ss_s = sm + KSTAGES * STAGE_WORDS;
    float* cs_s = ss_s + TBN;

    const int bz = blockIdx.z;
    const float* Bp = Bm + (size_t)bz * sB;
    float*       Cp = Cm + (size_t)bz * sC;
    const float* attB = GATE ? (gAtt + (size_t)bz * C2C * PP) : nullptr;

    const int m0 = blockIdx.y * TBM, n0 = blockIdx.x * TBN;
    const int tid  = threadIdx.x;
    const int lane = tid & 31, warp = tid >> 5;
    const int wm = warp % WM, wn = warp / WM;
    const int g = lane >> 2, tig = lane & 3;

    const int aRow = tid >> 3, aCc = (tid & 7) << 2;
    const int bRow = tid / (TBN / 4), bCc = (tid % (TBN / 4)) << 2;

    if (GATE) {
        if (tid < TBN)            ss_s[tid] = gSs[(size_t)bz * PP + n0 + tid];
        else if (tid < TBN + 128) cs_s[tid - TBN] = gCs[(size_t)bz * C2C + tid - TBN];
    }

    auto issue = [&](int kt) {
        const int k0 = kt * BK;
        float* As = sm + (kt % KSTAGES) * STAGE_WORDS;
        float* Bs = As + A_WORDS;
#pragma unroll
        for (int i = 0; i < A_PASSES; i++) {
            int r = aRow + i * 64;
            uint32_t dst = (uint32_t)__cvta_generic_to_shared(As + r * AS_STRIDE + aCc);
            const float* src = A + (size_t)(m0 + r) * K + k0 + aCc;
            cp16_sz(dst, src, (m0 + r < M) ? 16 : 0);
        }
#pragma unroll
        for (int i = 0; i < B_PASSES; i++) {
            int rr = bRow + i * B_ROWS_PER_PASS;
            int r = k0 + rr;
            uint32_t dst = (uint32_t)__cvta_generic_to_shared(Bs + rr * BS_STRIDE + bCc);
            const float* src;
            if (!GATE) src = Bp + (size_t)r * N + n0 + bCc;
            else       src = (r < C2C) ? (Bp + (size_t)r * PP + n0 + bCc)
                                       : (attB + (size_t)(r - C2C) * PP + n0 + bCc);
            cp16(dst, src);
        }
        cp_commit();
    };

    float acc[2][8][4];
#pragma unroll
    for (int mi = 0; mi < 2; mi++)
#pragma unroll
        for (int ni = 0; ni < 8; ni++)
#pragma unroll
            for (int r = 0; r < 4; r++) acc[mi][ni][r] = 0.f;

    const int KT = K / BK;
    issue(0);
    if (KT > 1) issue(1);

    for (int kt = 0; kt < KT; kt++) {
        if (kt + 1 < KT) { asm volatile("cp.async.wait_group 1;\n" ::: "memory"); }
        else             { asm volatile("cp.async.wait_group 0;\n" ::: "memory"); }
        __syncthreads();
        if (kt + 2 < KT) issue(kt + 2);

        const float* As = sm + (kt % KSTAGES) * STAGE_WORDS;
        const float* Bs = As + A_WORDS;
        const int k0 = kt * BK;

#pragma unroll
        for (int kk = 0; kk < 4; kk++) {
            const int kb = kk * 8;
            uint32_t a[2][4];
#pragma unroll
            for (int mi = 0; mi < 2; mi++) {
                int m = wm * 32 + mi * 16 + g;
                a[mi][0] = f2tf32(As[m * AS_STRIDE + kb + tig]);
                a[mi][1] = f2tf32(As[(m + 8) * AS_STRIDE + kb + tig]);
                a[mi][2] = f2tf32(As[m * AS_STRIDE + kb + tig + 4]);
                a[mi][3] = f2tf32(As[(m + 8) * AS_STRIDE + kb + tig + 4]);
            }
            uint32_t b[8][2];
            if (!GATE) {
#pragma unroll
                for (int ni = 0; ni < 8; ni++) {
                    int n = wn * 64 + ni * 8 + g;
                    b[ni][0] = f2tf32(Bs[(kb + tig) * BS_STRIDE + n]);
                    b[ni][1] = f2tf32(Bs[(kb + tig + 4) * BS_STRIDE + n]);
                }
            } else {
                int kr0 = k0 + kb + tig, kr1 = kr0 + 4;
                float cs0 = (kr0 >= C2C) ? cs_s[kr0 - C2C] : 0.f;
                float cs1 = (kr1 >= C2C) ? cs_s[kr1 - C2C] : 0.f;
#pragma unroll
                for (int ni = 0; ni < 8; ni++) {
                    int n = wn * 64 + ni * 8 + g;
                    float s0 = (kr0 < C2C) ? ss_s[n] : cs0;
                    float s1 = (kr1 < C2C) ? ss_s[n] : cs1;
                    b[ni][0] = f2tf32(Bs[(kb + tig) * BS_STRIDE + n] * s0);
                    b[ni][1] = f2tf32(Bs[(kb + tig + 4) * BS_STRIDE + n] * s1);
                }
            }
#pragma unroll
            for (int mi = 0; mi < 2; mi++)
#pragma unroll
                for (int ni = 0; ni < 8; ni++)
                    mma_tf32(acc[mi][ni], a[mi], b[ni]);
        }
    }

#pragma unroll
    for (int mi = 0; mi < 2; mi++) {
        int row_lo = m0 + wm * 32 + mi * 16 + g;
        int row_hi = row_lo + 8;
        float blo = (row_lo < M) ? bias[row_lo] : 0.f;
        float bhi = (row_hi < M) ? bias[row_hi] : 0.f;
#pragma unroll
        for (int ni = 0; ni < 8; ni++) {
            int col = n0 + wn * 64 + ni * 8 + tig * 2;
            float v0 = acc[mi][ni][0] + blo, v1 = acc[mi][ni][1] + blo;
            float v2 = acc[mi][ni][2] + bhi, v3 = acc[mi][ni][3] + bhi;
            if (ACT == 1) { v0 = fmaxf(v0, 0.f); v1 = fmaxf(v1, 0.f);
                            v2 = fmaxf(v2, 0.f); v3 = fmaxf(v3, 0.f); }
            if (ACT == 2) { v0 = tanhf(v0); v1 = tanhf(v1);
                            v2 = tanhf(v2); v3 = tanhf(v3); }
            if (row_lo < M) *(float2*)(Cp + (size_t)row_lo * N + col) = make_float2(v0, v1);
            if (row_hi < M) *(float2*)(Cp + (size_t)row_hi * N + col) = make_float2(v2, v3);
        }
    }
}

// ---------------- conv-fused GEMM: C = tanh(A * dwconv(X) + bias) ---------------
// B[r][n] = depthwise 7-tap conv (DIR=1 horizontal, DIR=2 vertical) of X channel r
// at pixel n, + cb[r]. Tile 128M x 256N (TBN = exactly 2 image rows), BK=32,
// register-staged double buffer (conv arithmetic precludes cp.async for B).
template<int DIR>
__global__ __launch_bounds__(512) void gemm_conv(
    const float* __restrict__ A, const float* __restrict__ bias,
    const float* __restrict__ X, size_t sX,
    const float* __restrict__ w7, const float* __restrict__ cb,
    float* __restrict__ Cm, int M, int K, int N, size_t sC)
{
    extern __shared__ float sm[];
    float* AsB[2] = { sm,           sm + CV_STAGE };
    // B region starts CV_AW into each stage

    const int bz = blockIdx.z;
    const float* Xp = X + (size_t)bz * sX;
    float*       Cp = Cm + (size_t)bz * sC;

    const int m0 = 0, n0 = blockIdx.x * CV_BN;
    const int tid  = threadIdx.x;
    const int lane = tid & 31, warp = tid >> 5;
    const int wm = warp & 3, wn = warp >> 2;     // 4m x 4n, warp tile 32x64
    const int g = lane >> 2, tig = lane & 3;

    const int aRow = tid >> 3, aCc = (tid & 7) << 2;   // 2 passes of 64 rows
    const int bRow = tid >> 6, bCc = (tid & 63) << 2;  // 4 passes of 8 rows

    float4 ra[2], rb[4];

    auto loadA = [&](int k0) {
#pragma unroll
        for (int i = 0; i < 2; i++) {
            int r = m0 + aRow + i * 64;
            ra[i] = (r < M) ? *(const float4*)(A + (size_t)r * K + k0 + aCc)
                            : make_float4(0.f, 0.f, 0.f, 0.f);
        }
    };
    auto loadB = [&](int k0) {
#pragma unroll
        for (int i = 0; i < 4; i++) {
            int c = k0 + bRow + i * 8;          // channel (k index)
            int p = n0 + bCc;                    // global pixel
            float bb = cb[c];
            const float* wc = w7 + c * 7;
            float o[4];
            if (DIR == 1) {
                int w4 = p & (WW - 1);
                const float* xr = Xp + (size_t)c * PP + (p - w4);
                float v[10];
                load_win10(xr, w4, v);
#pragma unroll
                for (int jj = 0; jj < 4; jj++) {
                    float s = bb;
#pragma unroll
                    for (int t = 0; t < 7; t++) s = fmaf(v[jj + t], wc[t], s);
                    o[jj] = s;
                }
            } else {
                int h = p >> 7;
                int wc4 = p & (WW - 1);
                const float* xb = Xp + (size_t)c * PP + wc4;
                float4 vt[7];
#pragma unroll
                for (int t = 0; t < 7; t++) {
                    int hh = h - 3 + t;
                    vt[t] = (hh >= 0 && hh < HH) ? *(const float4*)(xb + hh * WW)
                                                 : make_float4(0.f, 0.f, 0.f, 0.f);
                }
                float s0 = bb, s1 = bb, s2 = bb, s3 = bb;
#pragma unroll
                for (int t = 0; t < 7; t++) {
                    float wv = wc[t];
                    s0 = fmaf(vt[t].x, wv, s0);
                    s1 = fmaf(vt[t].y, wv, s1);
                    s2 = fmaf(vt[t].z, wv, s2);
                    s3 = fmaf(vt[t].w, wv, s3);
                }
                o[0] = s0; o[1] = s1; o[2] = s2; o[3] = s3;
            }
            rb[i] = make_float4(o[0], o[1], o[2], o[3]);
        }
    };
    auto stsAB = [&](int buf) {
        float* As = AsB[buf];
        float* Bs = As + CV_AW;
#pragma unroll
        for (int i = 0; i < 2; i++)
            *(float4*)&As[(aRow + i * 64) * AS_STRIDE + aCc] = ra[i];
#pragma unroll
        for (int i = 0; i < 4; i++)
            *(float4*)&Bs[(bRow + i * 8) * CV_BSTR + bCc] = rb[i];
    };

    float acc[2][8][4];
#pragma unroll
    for (int mi = 0; mi < 2; mi++)
#pragma unroll
        for (int ni = 0; ni < 8; ni++)
#pragma unroll
            for (int r = 0; r < 4; r++) acc[mi][ni][r] = 0.f;

    const int KT = K / BK;
    loadA(0); loadB(0);
    stsAB(0);
    __syncthreads();

    int buf = 0;
    for (int kt = 0;;) {
        const int knext = kt + 1;
        if (knext < KT) { loadA(knext * BK); loadB(knext * BK); }

        const float* As = AsB[buf];
        const float* Bs = As + CV_AW;
#pragma unroll
        for (int kk = 0; kk < 4; kk++) {
            const int kb = kk * 8;
            uint32_t a[2][4];
#pragma unroll
            for (int mi = 0; mi < 2; mi++) {
                int m = wm * 32 + mi * 16 + g;
                a[mi][0] = f2tf32(As[m * AS_STRIDE + kb + tig]);
                a[mi][1] = f2tf32(As[(m + 8) * AS_STRIDE + kb + tig]);
                a[mi][2] = f2tf32(As[m * AS_STRIDE + kb + tig + 4]);
                a[mi][3] = f2tf32(As[(m + 8) * AS_STRIDE + kb + tig + 4]);
            }
            uint32_t b[8][2];
#pragma unroll
            for (int ni = 0; ni < 8; ni++) {
                int n = wn * 64 + ni * 8 + g;
                b[ni][0] = f2tf32(Bs[(kb + tig) * CV_BSTR + n]);
                b[ni][1] = f2tf32(Bs[(kb + tig + 4) * CV_BSTR + n]);
            }
#pragma unroll
            for (int mi = 0; mi < 2; mi++)
#pragma unroll
                for (int ni = 0; ni < 8; ni++)
                    mma_tf32(acc[mi][ni], a[mi], b[ni]);
        }

        if (knext >= KT) break;
        stsAB(buf ^ 1);
        __syncthreads();
        buf ^= 1;
        kt = knext;
    }

#pragma unroll
    for (int mi = 0; mi < 2; mi++) {
        int row_lo = m0 + wm * 32 + mi * 16 + g;
        int row_hi = row_lo + 8;
        float blo = (row_lo < M) ? bias[row_lo] : 0.f;
        float bhi = (row_hi < M) ? bias[row_hi] : 0.f;
#pragma unroll
        for (int ni = 0; ni < 8; ni++) {
            int col = n0 + wn * 64 + ni * 8 + tig * 2;
            float v0 = tanhf(acc[mi][ni][0] + blo), v1 = tanhf(acc[mi][ni][1] + blo);
            float v2 = tanhf(acc[mi][ni][2] + bhi), v3 = tanhf(acc[mi][ni][3] + bhi);
            if (row_lo < M) *(float2*)(Cp + (size_t)row_lo * N + col) = make_float2(v0, v1);
            if (row_hi < M) *(float2*)(Cp + (size_t)row_hi * N + col) = make_float2(v2, v3);
        }
    }
}

// ---------------- FSA horizontal, 4 outputs/thread -----------------------------
__global__ void fsa_h4(const float* __restrict__ x, size_t sX,
                       const float* __restrict__ kern, float* __restrict__ out)
{
    int idx = blockIdx.x * 256 + threadIdx.x;
    if (idx >= NB * C2C * HH * (WW / 4)) return;
    int w4 = (idx & 31) << 2;
    int row = idx >> 5;
    int h = row % HH, c = (row / HH) % C2C, b = row / (HH * C2C);
    const float* xr = x + (size_t)b * sX + (size_t)c * PP + h * WW;
    float v[10];
    load_win10(xr, w4, v);
    const float* kb_ = kern + ((size_t)b * GKC + (size_t)(c >> 4) * 5) * PP + h * WW + w4;
    float4 k0 = *(const float4*)(kb_);
    float4 k1 = *(const float4*)(kb_ + PP);
    float4 k2 = *(const float4*)(kb_ + 2 * PP);
    float4 k3 = *(const float4*)(kb_ + 3 * PP);
    float4 k4 = *(const float4*)(kb_ + 4 * PP);
    float K0[4] = {k0.x, k0.y, k0.z, k0.w};
    float K1[4] = {k1.x, k1.y, k1.z, k1.w};
    float K2[4] = {k2.x, k2.y, k2.z, k2.w};
    float K3[4] = {k3.x, k3.y, k3.z, k3.w};
    float K4[4] = {k4.x, k4.y, k4.z, k4.w};
    float o[4];
#pragma unroll
    for (int i = 0; i < 4; i++) {
        float t0 = (v[i] + v[i + 1]) * 0.5f;
        float t4 = (v[i + 5] + v[i + 6]) * 0.5f;
        float s = t0 * K0[i];
        s = fmaf(v[i + 2], K1[i], s);
        s = fmaf(v[i + 3], K2[i], s);
        s = fmaf(v[i + 4], K3[i], s);
        s = fmaf(t4, K4[i], s);
        o[i] = s;
    }
    *(float4*)(out + ((size_t)b * C2C + c) * PP + h * WW + w4) = make_float4(o[0], o[1], o[2], o[3]);
}

// ---------------- FSA vertical, 4 outputs/thread --------------------------------
__global__ void fsa_v4(const float* __restrict__ x, size_t sX,
                       const float* __restrict__ kern, float* __restrict__ out)
{
    int idx = blockIdx.x * 256 + threadIdx.x;
    if (idx >= NB * C2C * (HH / 4) * WW) return;
    int w = idx % WW;
    int h4 = ((idx / WW) & 31) << 2;
    int c = (idx / (WW * 32)) % C2C;
    int b = idx / (WW * 32 * C2C);
    const float* xc = x + (size_t)b * sX + (size_t)c * PP;
    float v[10];
#pragma unroll
    for (int t = 0; t < 10; t++) {
        int hi = h4 - 3 + t;
        v[t] = (hi >= 0 && hi < HH) ? xc[hi * WW + w] : 0.f;
    }
    const float* kb_ = kern + ((size_t)b * GKC + (size_t)(c >> 4) * 5) * PP + h4 * WW + w;
    float* ob = out + ((size_t)b * C2C + c) * PP + h4 * WW + w;
#pragma unroll
    for (int i = 0; i < 4; i++) {
        float t0 = (v[i] + v[i + 1]) * 0.5f;
        float t4 = (v[i + 5] + v[i + 6]) * 0.5f;
        float s = t0 * kb_[i * WW];
        s = fmaf(v[i + 2], kb_[PP + i * WW], s);
        s = fmaf(v[i + 3], kb_[2 * PP + i * WW], s);
        s = fmaf(v[i + 4], kb_[3 * PP + i * WW], s);
        s = fmaf(t4, kb_[4 * PP + i * WW], s);
        ob[i * WW] = s;
    }
}

// ---------------- reductions / gating -------------------------------------------
__global__ void reduce_mean_p(const float* __restrict__ x, float* __restrict__ out)
{
    int bc = blockIdx.x;
    const float* xr = x + (size_t)bc * PP;
    float s = 0.f;
    for (int i = threadIdx.x; i < PP; i += 256) s += xr[i];
    __shared__ float sm[256];
    sm[threadIdx.x] = s; __syncthreads();
    for (int st = 128; st > 0; st >>= 1) {
        if (threadIdx.x < st) sm[threadIdx.x] += sm[threadIdx.x + st];
        __syncthreads();
    }
    if (threadIdx.x == 0) out[bc] = sm[0] * (1.f / PP);
}

__global__ void ssig_xcmean(const float* __restrict__ xconv,
                            const float* __restrict__ atmean,
                            float* __restrict__ ssig, float* __restrict__ xcm)
{
    int b = blockIdx.y;
    int p = blockIdx.x * 256 + threadIdx.x;
    __shared__ float am[C2C];
    if (threadIdx.x < C2C) am[threadIdx.x] = atmean[b * C2C + threadIdx.x];
    __syncthreads();
    const float* xr = xconv + (size_t)b * C2C * PP + p;
    float s = 0.f, m = 0.f;
#pragma unroll 8
    for (int c = 0; c < C2C; c++) {
        float v = xr[(size_t)c * PP];
        s = fmaf(am[c], v, s);
        m += v;
    }
    s *= (1.f / C2C);
    ssig[b * PP + p] = 1.f / (1.f + expf(-s));
    xcm[b * PP + p] = m * (1.f / C2C);
}

__global__ void csig_kernel(const float* __restrict__ attn,
                            const float* __restrict__ xcmean,
                            float* __restrict__ out)
{
    int bc = blockIdx.x;
    int b = bc / C2C;
    const float* ar = attn + (size_t)bc * PP;
    const float* xm = xcmean + (size_t)b * PP;
    float s = 0.f;
    for (int i = threadIdx.x; i < PP; i += 256) s = fmaf(ar[i], xm[i], s);
    __shared__ float sm[256];
    sm[threadIdx.x] = s; __syncthreads();
    for (int st = 128; st > 0; st >>= 1) {
        if (threadIdx.x < st) sm[threadIdx.x] += sm[threadIdx.x + st];
        __syncthreads();
    }
    if (threadIdx.x == 0) {
        float v = sm[0] * (1.f / PP);
        out[bc] = 1.f / (1.f + expf(-v));
    }
}

// ---------------- host orchestration --------------------------------------------
extern "C" void kernel_launch(void* const* d_in, const int* in_sizes, int n_in,
                              void* d_out, int out_size)
{
    const float* x         = (const float*)d_in[0];
    const float* proj_in_w = (const float*)d_in[1];
    const float* proj_in_b = (const float*)d_in[2];
    const float* hk_dw_w   = (const float*)d_in[3];
    const float* hk_dw_b   = (const float*)d_in[4];
    const float* hk_pw_w   = (const float*)d_in[5];
    const float* hk_pw_b   = (const float*)d_in[6];
    const float* vk_dw_w   = (const float*)d_in[7];
    const float* vk_dw_b   = (const float*)d_in[8];
    const float* vk_pw_w   = (const float*)d_in[9];
    const float* vk_pw_b   = (const float*)d_in[10];
    const float* cb_w1     = (const float*)d_in[11];
    const float* cb_b1     = (const float*)d_in[12];
    const float* cb_w2     = (const float*)d_in[13];
    const float* cb_b2     = (const float*)d_in[14];
    const float* proj_out_w= (const float*)d_in[15];
    const float* proj_out_b= (const float*)d_in[16];
    float* out = (float*)d_out;

    static int smem_set = 0;
    if (!smem_set) {
        cudaFuncSetAttribute(gemm_tc<0,0,8>, cudaFuncAttributeMaxDynamicSharedMemorySize, GSMEM_BYTES);
        cudaFuncSetAttribute(gemm_tc<0,1,8>, cudaFuncAttributeMaxDynamicSharedMemorySize, GSMEM_BYTES);
        cudaFuncSetAttribute(gemm_tc<0,0,4>, cudaFuncAttributeMaxDynamicSharedMemorySize, GSMEM_BYTES);
        cudaFuncSetAttribute(gemm_tc<1,0,4>, cudaFuncAttributeMaxDynamicSharedMemorySize, GSMEM_BYTES);
        cudaFuncSetAttribute(gemm_conv<1>,   cudaFuncAttributeMaxDynamicSharedMemorySize, CVSMEM_BYTES);
        cudaFuncSetAttribute(gemm_conv<2>,   cudaFuncAttributeMaxDynamicSharedMemorySize, CVSMEM_BYTES);
        smem_set = 1;
    }

    float *p_h, *p_mid, *p_xconv, *p_k, *p_attnh, *p_attn;
    float *p_atmean, *p_xcmean, *p_ssig, *p_csig;
    cudaGetSymbolAddress((void**)&p_h,      g_h);
    cudaGetSymbolAddress((void**)&p_mid,    g_mid);
    cudaGetSymbolAddress((void**)&p_xconv,  g_xconv);
    cudaGetSymbolAddress((void**)&p_k,      g_k);
    cudaGetSymbolAddress((void**)&p_attnh,  g_attnh);
    cudaGetSymbolAddress((void**)&p_attn,   g_attn);
    cudaGetSymbolAddress((void**)&p_atmean, g_atmean);
    cudaGetSymbolAddress((void**)&p_xcmean, g_xcmean);
    cudaGetSymbolAddress((void**)&p_ssig,   g_ssig);
    cudaGetSymbolAddress((void**)&p_csig,   g_csig);

    const int N = PP;
    const int eb4 = (NB * C2C * PP / 4) / 256;

    // 1) proj_in (M=256,K=256) — BIG tile
    gemm_tc<0,0,8><<<dim3(N/128, 1, NB), 512, GSMEM_BYTES>>>(proj_in_w, proj_in_b, x, p_h,
        256, 256, N, (size_t)256*PP, (size_t)256*PP, nullptr, nullptr, nullptr);
    // 2) cb hidden = relu (M=64,K=128) — SMALL tile
    gemm_tc<1,0,4><<<dim3(N/256, 1, NB), 512, GSMEM_BYTES>>>(cb_w1, cb_b1, p_h, p_mid,
        64, 128, N, (size_t)256*PP, (size_t)64*PP, nullptr, nullptr, nullptr);
    // 3) x_conv (M=128,K=64) — SMALL tile
    gemm_tc<0,0,4><<<dim3(N/256, 1, NB), 512, GSMEM_BYTES>>>(cb_w2, cb_b2, p_mid, p_xconv,
        128, 64, N, (size_t)64*PP, (size_t)C2C*PP, nullptr, nullptr, nullptr);
    // 4+5) kh = tanh(hk_pw · dwconv_h(x2)) — conv fused into B loader
    gemm_conv<1><<<dim3(N/256, 1, NB), 512, CVSMEM_BYTES>>>(hk_pw_w, hk_pw_b,
        p_h + (size_t)C2C*PP, (size_t)256*PP, hk_dw_w, hk_dw_b, p_k,
        GKC, 128, N, (size_t)GKC*PP);
    // 6) attn_h
    fsa_h4<<<eb4, 256>>>(p_h + (size_t)C2C*PP, (size_t)256*PP, p_k, p_attnh);
    // 7+8) kv = tanh(vk_pw · dwconv_v(attn_h)) — conv fused into B loader
    gemm_conv<2><<<dim3(N/256, 1, NB), 512, CVSMEM_BYTES>>>(vk_pw_w, vk_pw_b,
        p_attnh, (size_t)C2C*PP, vk_dw_w, vk_dw_b, p_k,
        GKC, 128, N, (size_t)GKC*PP);
    // 9) attn
    fsa_v4<<<eb4, 256>>>(p_attnh, (size_t)C2C*PP, p_k, p_attn);
    // 10) at_mean
    reduce_mean_p<<<NB*C2C, 256>>>(p_attn, p_atmean);
    // 11) fused ssig + xcmean
    ssig_xcmean<<<dim3(PP/256, NB), 256>>>(p_xconv, p_atmean, p_ssig, p_xcmean);
    // 12) c_sig
    csig_kernel<<<NB*C2C, 256>>>(p_attn, p_xcmean, p_csig);
    // 13) proj_out with fused gating/concat (M=256,K=256) — BIG tile
    gemm_tc<0,1,8><<<dim3(N/128, 1, NB), 512, GSMEM_BYTES>>>(proj_out_w, proj_out_b, p_xconv, out,
        256, 256, N, (size_t)C2C*PP, (size_t)256*PP, p_attn, p_ssig, p_csig);
}

// round 11
// speedup vs baseline: 1.0542x; 1.0542x over previous
#include <cuda_runtime.h>
#include <math.h>
#include <stdint.h>

#define NB 4
#define C2C 128
#define HH 128
#define WW 128
#define PP (HH*WW)          // 16384
#define GKC 40

#define BK 32
#define AS_STRIDE 36
#define KSTAGES 3
#define MAX_STAGE_WORDS 13568
#define GSMEM_WORDS (KSTAGES*MAX_STAGE_WORDS + 384)
#define GSMEM_BYTES (GSMEM_WORDS*4)       // 164352

// conv-GEMM v2: 64M x 128N tile, 256 threads, 2-stage register-staged
#define CB_M 64
#define CB_N 128
#define CB_BSTR 136
#define CB_AW (CB_M*AS_STRIDE)            // 2304
#define CB_BW (BK*CB_BSTR)                // 4352
#define CB_STAGE (CB_AW+CB_BW)            // 6656
#define CBSMEM_BYTES (2*CB_STAGE*4)       // 53248

// ---------------- scratch -----------------------------------------------------
__device__ float g_h[(size_t)NB*256*PP];
__device__ float g_mid[(size_t)NB*64*PP];
__device__ float g_xconv[(size_t)NB*C2C*PP];
__device__ float g_k[(size_t)NB*GKC*PP];
__device__ float g_attnh[(size_t)NB*C2C*PP];
__device__ float g_attn[(size_t)NB*C2C*PP];
__device__ float g_atmean[NB*C2C];
__device__ float g_xcmean[NB*PP];
__device__ float g_ssig[NB*PP];
__device__ float g_csig[NB*C2C];

// ---------------- tf32 / cp.async helpers --------------------------------------
__device__ __forceinline__ uint32_t f2tf32(float x) {
    uint32_t u;
    asm("cvt.rna.tf32.f32 %0, %1;" : "=r"(u) : "f"(x));
    return u;
}
__device__ __forceinline__ void mma_tf32(float c[4], const uint32_t a[4], const uint32_t b[2]) {
    asm volatile(
        "mma.sync.aligned.m16n8k8.row.col.f32.tf32.tf32.f32 "
        "{%0,%1,%2,%3}, {%4,%5,%6,%7}, {%8,%9}, {%0,%1,%2,%3};\n"
        : "+f"(c[0]), "+f"(c[1]), "+f"(c[2]), "+f"(c[3])
        : "r"(a[0]), "r"(a[1]), "r"(a[2]), "r"(a[3]), "r"(b[0]), "r"(b[1]));
}
__device__ __forceinline__ void cp16(uint32_t dst, const void* src) {
    asm volatile("cp.async.cg.shared.global [%0], [%1], 16;\n"
                 :: "r"(dst), "l"(src) : "memory");
}
__device__ __forceinline__ void cp16_sz(uint32_t dst, const void* src, int sz) {
    asm volatile("cp.async.cg.shared.global [%0], [%1], 16, %2;\n"
                 :: "r"(dst), "l"(src), "r"(sz) : "memory");
}
__device__ __forceinline__ void cp_commit() {
    asm volatile("cp.async.commit_group;\n" ::: "memory");
}

// ---------------- window loader (horizontal, 10 taps around w4) ---------------
__device__ __forceinline__ void load_win10(const float* __restrict__ xr, int w4, float v[10]) {
    if (w4 >= 4 && w4 + 8 <= WW) {
        float4 A = *(const float4*)(xr + w4 - 4);
        float4 Bv = *(const float4*)(xr + w4);
        float4 Cv = *(const float4*)(xr + w4 + 4);
        v[0] = A.y;  v[1] = A.z;  v[2] = A.w;
        v[3] = Bv.x; v[4] = Bv.y; v[5] = Bv.z; v[6] = Bv.w;
        v[7] = Cv.x; v[8] = Cv.y; v[9] = Cv.z;
    } else {
#pragma unroll
        for (int t = 0; t < 10; t++) {
            int wi = w4 - 3 + t;
            v[t] = (wi >= 0 && wi < WW) ? xr[wi] : 0.f;
        }
    }
}

// ---------------- tf32 GEMM v6 (unchanged — R9 best) ----------------------------
template<int ACT, int GATE, int WM>
__global__ __launch_bounds__(512) void gemm_tc(
    const float* __restrict__ A, const float* __restrict__ bias,
    const float* __restrict__ Bm, float* __restrict__ Cm,
    int M, int K, int N, size_t sB, size_t sC,
    const float* __restrict__ gAtt, const float* __restrict__ gSs,
    const float* __restrict__ gCs)
{
    constexpr int WN = 16 / WM;
    constexpr int TBM = WM * 32;
    constexpr int TBN = WN * 64;
    constexpr int BS_STRIDE = TBN + 8;
    constexpr int A_WORDS = TBM * AS_STRIDE;
    constexpr int B_WORDS = BK * BS_STRIDE;
    constexpr int STAGE_WORDS = A_WORDS + B_WORDS;
    constexpr int A_PASSES = TBM / 64;
    constexpr int B_PASSES = TBN / 64;
    constexpr int B_ROWS_PER_PASS = 2048 / TBN;

    extern __shared__ float sm[];
    float* ss_s = sm + KSTAGES * STAGE_WORDS;
    float* cs_s = ss_s + TBN;

    const int bz = blockIdx.z;
    const float* Bp = Bm + (size_t)bz * sB;
    float*       Cp = Cm + (size_t)bz * sC;
    const float* attB = GATE ? (gAtt + (size_t)bz * C2C * PP) : nullptr;

    const int m0 = blockIdx.y * TBM, n0 = blockIdx.x * TBN;
    const int tid  = threadIdx.x;
    const int lane = tid & 31, warp = tid >> 5;
    const int wm = warp % WM, wn = warp / WM;
    const int g = lane >> 2, tig = lane & 3;

    const int aRow = tid >> 3, aCc = (tid & 7) << 2;
    const int bRow = tid / (TBN / 4), bCc = (tid % (TBN / 4)) << 2;

    if (GATE) {
        if (tid < TBN)            ss_s[tid] = gSs[(size_t)bz * PP + n0 + tid];
        else if (tid < TBN + 128) cs_s[tid - TBN] = gCs[(size_t)bz * C2C + tid - TBN];
    }

    auto issue = [&](int kt) {
        const int k0 = kt * BK;
        float* As = sm + (kt % KSTAGES) * STAGE_WORDS;
        float* Bs = As + A_WORDS;
#pragma unroll
        for (int i = 0; i < A_PASSES; i++) {
            int r = aRow + i * 64;
            uint32_t dst = (uint32_t)__cvta_generic_to_shared(As + r * AS_STRIDE + aCc);
            const float* src = A + (size_t)(m0 + r) * K + k0 + aCc;
            cp16_sz(dst, src, (m0 + r < M) ? 16 : 0);
        }
#pragma unroll
        for (int i = 0; i < B_PASSES; i++) {
            int rr = bRow + i * B_ROWS_PER_PASS;
            int r = k0 + rr;
            uint32_t dst = (uint32_t)__cvta_generic_to_shared(Bs + rr * BS_STRIDE + bCc);
            const float* src;
            if (!GATE) src = Bp + (size_t)r * N + n0 + bCc;
            else       src = (r < C2C) ? (Bp + (size_t)r * PP + n0 + bCc)
                                       : (attB + (size_t)(r - C2C) * PP + n0 + bCc);
            cp16(dst, src);
        }
        cp_commit();
    };

    float acc[2][8][4];
#pragma unroll
    for (int mi = 0; mi < 2; mi++)
#pragma unroll
        for (int ni = 0; ni < 8; ni++)
#pragma unroll
            for (int r = 0; r < 4; r++) acc[mi][ni][r] = 0.f;

    const int KT = K / BK;
    issue(0);
    if (KT > 1) issue(1);

    for (int kt = 0; kt < KT; kt++) {
        if (kt + 1 < KT) { asm volatile("cp.async.wait_group 1;\n" ::: "memory"); }
        else             { asm volatile("cp.async.wait_group 0;\n" ::: "memory"); }
        __syncthreads();
        if (kt + 2 < KT) issue(kt + 2);

        const float* As = sm + (kt % KSTAGES) * STAGE_WORDS;
        const float* Bs = As + A_WORDS;
        const int k0 = kt * BK;

#pragma unroll
        for (int kk = 0; kk < 4; kk++) {
            const int kb = kk * 8;
            uint32_t a[2][4];
#pragma unroll
            for (int mi = 0; mi < 2; mi++) {
                int m = wm * 32 + mi * 16 + g;
                a[mi][0] = f2tf32(As[m * AS_STRIDE + kb + tig]);
                a[mi][1] = f2tf32(As[(m + 8) * AS_STRIDE + kb + tig]);
                a[mi][2] = f2tf32(As[m * AS_STRIDE + kb + tig + 4]);
                a[mi][3] = f2tf32(As[(m + 8) * AS_STRIDE + kb + tig + 4]);
            }
            uint32_t b[8][2];
            if (!GATE) {
#pragma unroll
                for (int ni = 0; ni < 8; ni++) {
                    int n = wn * 64 + ni * 8 + g;
                    b[ni][0] = f2tf32(Bs[(kb + tig) * BS_STRIDE + n]);
                    b[ni][1] = f2tf32(Bs[(kb + tig + 4) * BS_STRIDE + n]);
                }
            } else {
                int kr0 = k0 + kb + tig, kr1 = kr0 + 4;
                float cs0 = (kr0 >= C2C) ? cs_s[kr0 - C2C] : 0.f;
                float cs1 = (kr1 >= C2C) ? cs_s[kr1 - C2C] : 0.f;
#pragma unroll
                for (int ni = 0; ni < 8; ni++) {
                    int n = wn * 64 + ni * 8 + g;
                    float s0 = (kr0 < C2C) ? ss_s[n] : cs0;
                    float s1 = (kr1 < C2C) ? ss_s[n] : cs1;
                    b[ni][0] = f2tf32(Bs[(kb + tig) * BS_STRIDE + n] * s0);
                    b[ni][1] = f2tf32(Bs[(kb + tig + 4) * BS_STRIDE + n] * s1);
                }
            }
#pragma unroll
            for (int mi = 0; mi < 2; mi++)
#pragma unroll
                for (int ni = 0; ni < 8; ni++)
                    mma_tf32(acc[mi][ni], a[mi], b[ni]);
        }
    }

#pragma unroll
    for (int mi = 0; mi < 2; mi++) {
        int row_lo = m0 + wm * 32 + mi * 16 + g;
        int row_hi = row_lo + 8;
        float blo = (row_lo < M) ? bias[row_lo] : 0.f;
        float bhi = (row_hi < M) ? bias[row_hi] : 0.f;
#pragma unroll
        for (int ni = 0; ni < 8; ni++) {
            int col = n0 + wn * 64 + ni * 8 + tig * 2;
            float v0 = acc[mi][ni][0] + blo, v1 = acc[mi][ni][1] + blo;
            float v2 = acc[mi][ni][2] + bhi, v3 = acc[mi][ni][3] + bhi;
            if (ACT == 1) { v0 = fmaxf(v0, 0.f); v1 = fmaxf(v1, 0.f);
                            v2 = fmaxf(v2, 0.f); v3 = fmaxf(v3, 0.f); }
            if (ACT == 2) { v0 = tanhf(v0); v1 = tanhf(v1);
                            v2 = tanhf(v2); v3 = tanhf(v3); }
            if (row_lo < M) *(float2*)(Cp + (size_t)row_lo * N + col) = make_float2(v0, v1);
            if (row_hi < M) *(float2*)(Cp + (size_t)row_hi * N + col) = make_float2(v2, v3);
        }
    }
}

// ---------------- conv-fused GEMM v2: C = tanh(A * dwconv(X) + bias) ------------
// 256 threads, 64M x 128N tile (8 warps as 2m x 4n, 32x32 warp tiles).
// B[r][n] = 7-tap depthwise conv (DIR=1 horiz, DIR=2 vert) of X channel r + cb[r].
// TBN = 128 = exactly one image row.
template<int DIR>
__global__ __launch_bounds__(256) void gemm_conv(
    const float* __restrict__ A, const float* __restrict__ bias,
    const float* __restrict__ X, size_t sX,
    const float* __restrict__ w7, const float* __restrict__ cb,
    float* __restrict__ Cm, int M, int K, int N, size_t sC)
{
    extern __shared__ float sm[];
    float* AsB[2] = { sm, sm + CB_STAGE };

    const int bz = blockIdx.z;
    const float* Xp = X + (size_t)bz * sX;
    float*       Cp = Cm + (size_t)bz * sC;

    const int n0 = blockIdx.x * CB_N;           // one image row per block
    const int tid  = threadIdx.x;
    const int lane = tid & 31, warp = tid >> 5;
    const int wm = warp & 1, wn = warp >> 1;     // 2m x 4n
    const int g = lane >> 2, tig = lane & 3;

    const int aRow = tid >> 3, aCc = (tid & 7) << 2;   // 2 passes of 32 rows
    const int bRow = tid >> 5, bCc = (tid & 31) << 2;  // 4 passes of 8 rows

    float4 ra[2], rb[4];

    auto loadA = [&](int k0) {
#pragma unroll
        for (int i = 0; i < 2; i++) {
            int r = aRow + i * 32;
            ra[i] = (r < M) ? *(const float4*)(A + (size_t)r * K + k0 + aCc)
                            : make_float4(0.f, 0.f, 0.f, 0.f);
        }
    };
    auto loadB = [&](int k0) {
#pragma unroll
        for (int i = 0; i < 4; i++) {
            int c = k0 + bRow + i * 8;          // channel (k index)
            float bb = cb[c];
            const float* wc = w7 + c * 7;
            float o[4];
            if (DIR == 1) {
                int w4 = bCc;                    // pixel-in-row
                const float* xr = Xp + (size_t)c * PP + n0;
                float v[10];
                load_win10(xr, w4, v);
#pragma unroll
                for (int jj = 0; jj < 4; jj++) {
                    float s = bb;
#pragma unroll
                    for (int t = 0; t < 7; t++) s = fmaf(v[jj + t], wc[t], s);
                    o[jj] = s;
                }
            } else {
                int h = n0 >> 7;                 // constant per block
                const float* xb = Xp + (size_t)c * PP + bCc;
                float4 vt[7];
#pragma unroll
                for (int t = 0; t < 7; t++) {
                    int hh = h - 3 + t;
                    vt[t] = (hh >= 0 && hh < HH) ? *(const float4*)(xb + hh * WW)
                                                 : make_float4(0.f, 0.f, 0.f, 0.f);
                }
                float s0 = bb, s1 = bb, s2 = bb, s3 = bb;
#pragma unroll
                for (int t = 0; t < 7; t++) {
                    float wv = wc[t];
                    s0 = fmaf(vt[t].x, wv, s0);
                    s1 = fmaf(vt[t].y, wv, s1);
                    s2 = fmaf(vt[t].z, wv, s2);
                    s3 = fmaf(vt[t].w, wv, s3);
                }
                o[0] = s0; o[1] = s1; o[2] = s2; o[3] = s3;
            }
            rb[i] = make_float4(o[0], o[1], o[2], o[3]);
        }
    };
    auto stsAB = [&](int buf) {
        float* As = AsB[buf];
        float* Bs = As + CB_AW;
#pragma unroll
        for (int i = 0; i < 2; i++)
            *(float4*)&As[(aRow + i * 32) * AS_STRIDE + aCc] = ra[i];
#pragma unroll
        for (int i = 0; i < 4; i++)
            *(float4*)&Bs[(bRow + i * 8) * CB_BSTR + bCc] = rb[i];
    };

    float acc[2][4][4];
#pragma unroll
    for (int mi = 0; mi < 2; mi++)
#pragma unroll
        for (int ni = 0; ni < 4; ni++)
#pragma unroll
            for (int r = 0; r < 4; r++) acc[mi][ni][r] = 0.f;

    const int KT = K / BK;
    loadA(0); loadB(0);
    stsAB(0);
    __syncthreads();

    int buf = 0;
    for (int kt = 0;;) {
        const int knext = kt + 1;
        if (knext < KT) { loadA(knext * BK); loadB(knext * BK); }

        const float* As = AsB[buf];
        const float* Bs = As + CB_AW;
#pragma unroll
        for (int kk = 0; kk < 4; kk++) {
            const int kb = kk * 8;
            uint32_t a[2][4];
#pragma unroll
            for (int mi = 0; mi < 2; mi++) {
                int m = wm * 32 + mi * 16 + g;
                a[mi][0] = f2tf32(As[m * AS_STRIDE + kb + tig]);
                a[mi][1] = f2tf32(As[(m + 8) * AS_STRIDE + kb + tig]);
                a[mi][2] = f2tf32(As[m * AS_STRIDE + kb + tig + 4]);
                a[mi][3] = f2tf32(As[(m + 8) * AS_STRIDE + kb + tig + 4]);
            }
            uint32_t b[4][2];
#pragma unroll
            for (int ni = 0; ni < 4; ni++) {
                int n = wn * 32 + ni * 8 + g;
                b[ni][0] = f2tf32(Bs[(kb + tig) * CB_BSTR + n]);
                b[ni][1] = f2tf32(Bs[(kb + tig + 4) * CB_BSTR + n]);
            }
#pragma unroll
            for (int mi = 0; mi < 2; mi++)
#pragma unroll
                for (int ni = 0; ni < 4; ni++)
                    mma_tf32(acc[mi][ni], a[mi], b[ni]);
        }

        if (knext >= KT) break;
        stsAB(buf ^ 1);
        __syncthreads();
        buf ^= 1;
        kt = knext;
    }

#pragma unroll
    for (int mi = 0; mi < 2; mi++) {
        int row_lo = wm * 32 + mi * 16 + g;
        int row_hi = row_lo + 8;
        float blo = (row_lo < M) ? bias[row_lo] : 0.f;
        float bhi = (row_hi < M) ? bias[row_hi] : 0.f;
#pragma unroll
        for (int ni = 0; ni < 4; ni++) {
            int col = n0 + wn * 32 + ni * 8 + tig * 2;
            float v0 = tanhf(acc[mi][ni][0] + blo), v1 = tanhf(acc[mi][ni][1] + blo);
            float v2 = tanhf(acc[mi][ni][2] + bhi), v3 = tanhf(acc[mi][ni][3] + bhi);
            if (row_lo < M) *(float2*)(Cp + (size_t)row_lo * N + col) = make_float2(v0, v1);
            if (row_hi < M) *(float2*)(Cp + (size_t)row_hi * N + col) = make_float2(v2, v3);
        }
    }
}

// ---------------- FSA horizontal, 4 outputs/thread -----------------------------
__global__ void fsa_h4(const float* __restrict__ x, size_t sX,
                       const float* __restrict__ kern, float* __restrict__ out)
{
    int idx = blockIdx.x * 256 + threadIdx.x;
    if (idx >= NB * C2C * HH * (WW / 4)) return;
    int w4 = (idx & 31) << 2;
    int row = idx >> 5;
    int h = row % HH, c = (row / HH) % C2C, b = row / (HH * C2C);
    const float* xr = x + (size_t)b * sX + (size_t)c * PP + h * WW;
    float v[10];
    load_win10(xr, w4, v);
    const float* kb_ = kern + ((size_t)b * GKC + (size_t)(c >> 4) * 5) * PP + h * WW + w4;
    float4 k0 = *(const float4*)(kb_);
    float4 k1 = *(const float4*)(kb_ + PP);
    float4 k2 = *(const float4*)(kb_ + 2 * PP);
    float4 k3 = *(const float4*)(kb_ + 3 * PP);
    float4 k4 = *(const float4*)(kb_ + 4 * PP);
    float K0[4] = {k0.x, k0.y, k0.z, k0.w};
    float K1[4] = {k1.x, k1.y, k1.z, k1.w};
    float K2[4] = {k2.x, k2.y, k2.z, k2.w};
    float K3[4] = {k3.x, k3.y, k3.z, k3.w};
    float K4[4] = {k4.x, k4.y, k4.z, k4.w};
    float o[4];
#pragma unroll
    for (int i = 0; i < 4; i++) {
        float t0 = (v[i] + v[i + 1]) * 0.5f;
        float t4 = (v[i + 5] + v[i + 6]) * 0.5f;
        float s = t0 * K0[i];
        s = fmaf(v[i + 2], K1[i], s);
        s = fmaf(v[i + 3], K2[i], s);
        s = fmaf(v[i + 4], K3[i], s);
        s = fmaf(t4, K4[i], s);
        o[i] = s;
    }
    *(float4*)(out + ((size_t)b * C2C + c) * PP + h * WW + w4) = make_float4(o[0], o[1], o[2], o[3]);
}

// ---------------- FSA vertical, 4 outputs/thread --------------------------------
__global__ void fsa_v4(const float* __restrict__ x, size_t sX,
                       const float* __restrict__ kern, float* __restrict__ out)
{
    int idx = blockIdx.x * 256 + threadIdx.x;
    if (idx >= NB * C2C * (HH / 4) * WW) return;
    int w = idx % WW;
    int h4 = ((idx / WW) & 31) << 2;
    int c = (idx / (WW * 32)) % C2C;
    int b = idx / (WW * 32 * C2C);
    const float* xc = x + (size_t)b * sX + (size_t)c * PP;
    float v[10];
#pragma unroll
    for (int t = 0; t < 10; t++) {
        int hi = h4 - 3 + t;
        v[t] = (hi >= 0 && hi < HH) ? xc[hi * WW + w] : 0.f;
    }
    const float* kb_ = kern + ((size_t)b * GKC + (size_t)(c >> 4) * 5) * PP + h4 * WW + w;
    float* ob = out + ((size_t)b * C2C + c) * PP + h4 * WW + w;
#pragma unroll
    for (int i = 0; i < 4; i++) {
        float t0 = (v[i] + v[i + 1]) * 0.5f;
        float t4 = (v[i + 5] + v[i + 6]) * 0.5f;
        float s = t0 * kb_[i * WW];
        s = fmaf(v[i + 2], kb_[PP + i * WW], s);
        s = fmaf(v[i + 3], kb_[2 * PP + i * WW], s);
        s = fmaf(v[i + 4], kb_[3 * PP + i * WW], s);
        s = fmaf(t4, kb_[4 * PP + i * WW], s);
        ob[i * WW] = s;
    }
}

// ---------------- reductions / gating -------------------------------------------
__global__ void reduce_mean_p(const float* __restrict__ x, float* __restrict__ out)
{
    int bc = blockIdx.x;
    const float* xr = x + (size_t)bc * PP;
    float s = 0.f;
    for (int i = threadIdx.x; i < PP; i += 256) s += xr[i];
    __shared__ float sm[256];
    sm[threadIdx.x] = s; __syncthreads();
    for (int st = 128; st > 0; st >>= 1) {
        if (threadIdx.x < st) sm[threadIdx.x] += sm[threadIdx.x + st];
        __syncthreads();
    }
    if (threadIdx.x == 0) out[bc] = sm[0] * (1.f / PP);
}

__global__ void ssig_xcmean(const float* __restrict__ xconv,
                            const float* __restrict__ atmean,
                            float* __restrict__ ssig, float* __restrict__ xcm)
{
    int b = blockIdx.y;
    int p = blockIdx.x * 256 + threadIdx.x;
    __shared__ float am[C2C];
    if (threadIdx.x < C2C) am[threadIdx.x] = atmean[b * C2C + threadIdx.x];
    __syncthreads();
    const float* xr = xconv + (size_t)b * C2C * PP + p;
    float s = 0.f, m = 0.f;
#pragma unroll 8
    for (int c = 0; c < C2C; c++) {
        float v = xr[(size_t)c * PP];
        s = fmaf(am[c], v, s);
        m += v;
    }
    s *= (1.f / C2C);
    ssig[b * PP + p] = 1.f / (1.f + expf(-s));
    xcm[b * PP + p] = m * (1.f / C2C);
}

__global__ void csig_kernel(const float* __restrict__ attn,
                            const float* __restrict__ xcmean,
                            float* __restrict__ out)
{
    int bc = blockIdx.x;
    int b = bc / C2C;
    const float* ar = attn + (size_t)bc * PP;
    const float* xm = xcmean + (size_t)b * PP;
    float s = 0.f;
    for (int i = threadIdx.x; i < PP; i += 256) s = fmaf(ar[i], xm[i], s);
    __shared__ float sm[256];
    sm[threadIdx.x] = s; __syncthreads();
    for (int st = 128; st > 0; st >>= 1) {
        if (threadIdx.x < st) sm[threadIdx.x] += sm[threadIdx.x + st];
        __syncthreads();
    }
    if (threadIdx.x == 0) {
        float v = sm[0] * (1.f / PP);
        out[bc] = 1.f / (1.f + expf(-v));
    }
}

// ---------------- host orchestration --------------------------------------------
extern "C" void kernel_launch(void* const* d_in, const int* in_sizes, int n_in,
                              void* d_out, int out_size)
{
    const float* x         = (const float*)d_in[0];
    const float* proj_in_w = (const float*)d_in[1];
    const float* proj_in_b = (const float*)d_in[2];
    const float* hk_dw_w   = (const float*)d_in[3];
    const float* hk_dw_b   = (const float*)d_in[4];
    const float* hk_pw_w   = (const float*)d_in[5];
    const float* hk_pw_b   = (const float*)d_in[6];
    const float* vk_dw_w   = (const float*)d_in[7];
    const float* vk_dw_b   = (const float*)d_in[8];
    const float* vk_pw_w   = (const float*)d_in[9];
    const float* vk_pw_b   = (const float*)d_in[10];
    const float* cb_w1     = (const float*)d_in[11];
    const float* cb_b1     = (const float*)d_in[12];
    const float* cb_w2     = (const float*)d_in[13];
    const float* cb_b2     = (const float*)d_in[14];
    const float* proj_out_w= (const float*)d_in[15];
    const float* proj_out_b= (const float*)d_in[16];
    float* out = (float*)d_out;

    static int smem_set = 0;
    if (!smem_set) {
        cudaFuncSetAttribute(gemm_tc<0,0,8>, cudaFuncAttributeMaxDynamicSharedMemorySize, GSMEM_BYTES);
        cudaFuncSetAttribute(gemm_tc<0,1,8>, cudaFuncAttributeMaxDynamicSharedMemorySize, GSMEM_BYTES);
        cudaFuncSetAttribute(gemm_tc<0,0,4>, cudaFuncAttributeMaxDynamicSharedMemorySize, GSMEM_BYTES);
        cudaFuncSetAttribute(gemm_tc<1,0,4>, cudaFuncAttributeMaxDynamicSharedMemorySize, GSMEM_BYTES);
        cudaFuncSetAttribute(gemm_conv<1>,   cudaFuncAttributeMaxDynamicSharedMemorySize, CBSMEM_BYTES);
        cudaFuncSetAttribute(gemm_conv<2>,   cudaFuncAttributeMaxDynamicSharedMemorySize, CBSMEM_BYTES);
        smem_set = 1;
    }

    float *p_h, *p_mid, *p_xconv, *p_k, *p_attnh, *p_attn;
    float *p_atmean, *p_xcmean, *p_ssig, *p_csig;
    cudaGetSymbolAddress((void**)&p_h,      g_h);
    cudaGetSymbolAddress((void**)&p_mid,    g_mid);
    cudaGetSymbolAddress((void**)&p_xconv,  g_xconv);
    cudaGetSymbolAddress((void**)&p_k,      g_k);
    cudaGetSymbolAddress((void**)&p_attnh,  g_attnh);
    cudaGetSymbolAddress((void**)&p_attn,   g_attn);
    cudaGetSymbolAddress((void**)&p_atmean, g_atmean);
    cudaGetSymbolAddress((void**)&p_xcmean, g_xcmean);
    cudaGetSymbolAddress((void**)&p_ssig,   g_ssig);
    cudaGetSymbolAddress((void**)&p_csig,   g_csig);

    const int N = PP;
    const int eb4 = (NB * C2C * PP / 4) / 256;

    // 1) proj_in (M=256,K=256) — BIG tile
    gemm_tc<0,0,8><<<dim3(N/128, 1, NB), 512, GSMEM_BYTES>>>(proj_in_w, proj_in_b, x, p_h,
        256, 256, N, (size_t)256*PP, (size_t)256*PP, nullptr, nullptr, nullptr);
    // 2) cb hidden = relu (M=64,K=128) — SMALL tile
    gemm_tc<1,0,4><<<dim3(N/256, 1, NB), 512, GSMEM_BYTES>>>(cb_w1, cb_b1, p_h, p_mid,
        64, 128, N, (size_t)256*PP, (size_t)64*PP, nullptr, nullptr, nullptr);
    // 3) x_conv (M=128,K=64) — SMALL tile
    gemm_tc<0,0,4><<<dim3(N/256, 1, NB), 512, GSMEM_BYTES>>>(cb_w2, cb_b2, p_mid, p_xconv,
        128, 64, N, (size_t)64*PP, (size_t)C2C*PP, nullptr, nullptr, nullptr);
    // 4+5) kh = tanh(hk_pw · dwconv_h(x2)) — conv-fused, right-sized tile
    gemm_conv<1><<<dim3(N/CB_N, 1, NB), 256, CBSMEM_BYTES>>>(hk_pw_w, hk_pw_b,
        p_h + (size_t)C2C*PP, (size_t)256*PP, hk_dw_w, hk_dw_b, p_k,
        GKC, 128, N, (size_t)GKC*PP);
    // 6) attn_h
    fsa_h4<<<eb4, 256>>>(p_h + (size_t)C2C*PP, (size_t)256*PP, p_k, p_attnh);
    // 7+8) kv = tanh(vk_pw · dwconv_v(attn_h)) — conv-fused, right-sized tile
    gemm_conv<2><<<dim3(N/CB_N, 1, NB), 256, CBSMEM_BYTES>>>(vk_pw_w, vk_pw_b,
        p_attnh, (size_t)C2C*PP, vk_dw_w, vk_dw_b, p_k,
        GKC, 128, N, (size_t)GKC*PP);
    // 9) attn
    fsa_v4<<<eb4, 256>>>(p_attnh, (size_t)C2C*PP, p_k, p_attn);
    // 10) at_mean
    reduce_mean_p<<<NB*C2C, 256>>>(p_attn, p_atmean);
    // 11) fused ssig + xcmean
    ssig_xcmean<<<dim3(PP/256, NB), 256>>>(p_xconv, p_atmean, p_ssig, p_xcmean);
    // 12) c_sig
    csig_kernel<<<NB*C2C, 256>>>(p_attn, p_xcmean, p_csig);
    // 13) proj_out with fused gating/concat (M=256,K=256) — BIG tile
    gemm_tc<0,1,8><<<dim3(N/128, 1, NB), 512, GSMEM_BYTES>>>(proj_out_w, proj_out_b, p_xconv, out,
        256, 256, N, (size_t)C2C*PP, (size_t)256*PP, p_attn, p_ssig, p_csig);
}

// round 12
// speedup vs baseline: 1.0778x; 1.0224x over previous
#include <cuda_runtime.h>
#include <math.h>
#include <stdint.h>

#define NB 4
#define C2C 128
#define HH 128
#define WW 128
#define PP (HH*WW)          // 16384
#define GKC 40

#define BK 32
#define AS_STRIDE 36
#define KSTAGES 3
#define MAX_STAGE_WORDS 13568
#define GSMEM_WORDS (KSTAGES*MAX_STAGE_WORDS + 384)
#define GSMEM_BYTES (GSMEM_WORDS*4)       // 164352

// conv-GEMM v3: 64M x 128N tile, 512 threads (16 warps, 4m x 4n, 16x32 warp tiles)
#define CB_M 64
#define CB_N 128
#define CB_BSTR 136
#define CB_AW (CB_M*AS_STRIDE)            // 2304
#define CB_BW (BK*CB_BSTR)                // 4352
#define CB_STAGE (CB_AW+CB_BW)            // 6656
#define CBSMEM_BYTES (2*CB_STAGE*4)       // 53248

// ---------------- scratch -----------------------------------------------------
__device__ float g_h[(size_t)NB*256*PP];
__device__ float g_mid[(size_t)NB*64*PP];
__device__ float g_xconv[(size_t)NB*C2C*PP];
__device__ float g_k[(size_t)NB*GKC*PP];
__device__ float g_attnh[(size_t)NB*C2C*PP];
__device__ float g_attn[(size_t)NB*C2C*PP];
__device__ float g_atmean[NB*C2C];
__device__ float g_xcmean[NB*PP];
__device__ float g_ssig[NB*PP];
__device__ float g_csig[NB*C2C];

// ---------------- tf32 / cp.async helpers --------------------------------------
__device__ __forceinline__ uint32_t f2tf32(float x) {
    uint32_t u;
    asm("cvt.rna.tf32.f32 %0, %1;" : "=r"(u) : "f"(x));
    return u;
}
__device__ __forceinline__ void mma_tf32(float c[4], const uint32_t a[4], const uint32_t b[2]) {
    asm volatile(
        "mma.sync.aligned.m16n8k8.row.col.f32.tf32.tf32.f32 "
        "{%0,%1,%2,%3}, {%4,%5,%6,%7}, {%8,%9}, {%0,%1,%2,%3};\n"
        : "+f"(c[0]), "+f"(c[1]), "+f"(c[2]), "+f"(c[3])
        : "r"(a[0]), "r"(a[1]), "r"(a[2]), "r"(a[3]), "r"(b[0]), "r"(b[1]));
}
__device__ __forceinline__ void cp16(uint32_t dst, const void* src) {
    asm volatile("cp.async.cg.shared.global [%0], [%1], 16;\n"
                 :: "r"(dst), "l"(src) : "memory");
}
__device__ __forceinline__ void cp16_sz(uint32_t dst, const void* src, int sz) {
    asm volatile("cp.async.cg.shared.global [%0], [%1], 16, %2;\n"
                 :: "r"(dst), "l"(src), "r"(sz) : "memory");
}
__device__ __forceinline__ void cp_commit() {
    asm volatile("cp.async.commit_group;\n" ::: "memory");
}

// ---------------- window loader (horizontal, 10 taps around w4) ---------------
__device__ __forceinline__ void load_win10(const float* __restrict__ xr, int w4, float v[10]) {
    if (w4 >= 4 && w4 + 8 <= WW) {
        float4 A = *(const float4*)(xr + w4 - 4);
        float4 Bv = *(const float4*)(xr + w4);
        float4 Cv = *(const float4*)(xr + w4 + 4);
        v[0] = A.y;  v[1] = A.z;  v[2] = A.w;
        v[3] = Bv.x; v[4] = Bv.y; v[5] = Bv.z; v[6] = Bv.w;
        v[7] = Cv.x; v[8] = Cv.y; v[9] = Cv.z;
    } else {
#pragma unroll
        for (int t = 0; t < 10; t++) {
            int wi = w4 - 3 + t;
            v[t] = (wi >= 0 && wi < WW) ? xr[wi] : 0.f;
        }
    }
}

// ---------------- tf32 GEMM v6 (unchanged — best known) -------------------------
template<int ACT, int GATE, int WM>
__global__ __launch_bounds__(512) void gemm_tc(
    const float* __restrict__ A, const float* __restrict__ bias,
    const float* __restrict__ Bm, float* __restrict__ Cm,
    int M, int K, int N, size_t sB, size_t sC,
    const float* __restrict__ gAtt, const float* __restrict__ gSs,
    const float* __restrict__ gCs)
{
    constexpr int WN = 16 / WM;
    constexpr int TBM = WM * 32;
    constexpr int TBN = WN * 64;
    constexpr int BS_STRIDE = TBN + 8;
    constexpr int A_WORDS = TBM * AS_STRIDE;
    constexpr int B_WORDS = BK * BS_STRIDE;
    constexpr int STAGE_WORDS = A_WORDS + B_WORDS;
    constexpr int A_PASSES = TBM / 64;
    constexpr int B_PASSES = TBN / 64;
    constexpr int B_ROWS_PER_PASS = 2048 / TBN;

    extern __shared__ float sm[];
    float* ss_s = sm + KSTAGES * STAGE_WORDS;
    float* cs_s = ss_s + TBN;

    const int bz = blockIdx.z;
    const float* Bp = Bm + (size_t)bz * sB;
    float*       Cp = Cm + (size_t)bz * sC;
    const float* attB = GATE ? (gAtt + (size_t)bz * C2C * PP) : nullptr;

    const int m0 = blockIdx.y * TBM, n0 = blockIdx.x * TBN;
    const int tid  = threadIdx.x;
    const int lane = tid & 31, warp = tid >> 5;
    const int wm = warp % WM, wn = warp / WM;
    const int g = lane >> 2, tig = lane & 3;

    const int aRow = tid >> 3, aCc = (tid & 7) << 2;
    const int bRow = tid / (TBN / 4), bCc = (tid % (TBN / 4)) << 2;

    if (GATE) {
        if (tid < TBN)            ss_s[tid] = gSs[(size_t)bz * PP + n0 + tid];
        else if (tid < TBN + 128) cs_s[tid - TBN] = gCs[(size_t)bz * C2C + tid - TBN];
    }

    auto issue = [&](int kt) {
        const int k0 = kt * BK;
        float* As = sm + (kt % KSTAGES) * STAGE_WORDS;
        float* Bs = As + A_WORDS;
#pragma unroll
        for (int i = 0; i < A_PASSES; i++) {
            int r = aRow + i * 64;
            uint32_t dst = (uint32_t)__cvta_generic_to_shared(As + r * AS_STRIDE + aCc);
            const float* src = A + (size_t)(m0 + r) * K + k0 + aCc;
            cp16_sz(dst, src, (m0 + r < M) ? 16 : 0);
        }
#pragma unroll
        for (int i = 0; i < B_PASSES; i++) {
            int rr = bRow + i * B_ROWS_PER_PASS;
            int r = k0 + rr;
            uint32_t dst = (uint32_t)__cvta_generic_to_shared(Bs + rr * BS_STRIDE + bCc);
            const float* src;
            if (!GATE) src = Bp + (size_t)r * N + n0 + bCc;
            else       src = (r < C2C) ? (Bp + (size_t)r * PP + n0 + bCc)
                                       : (attB + (size_t)(r - C2C) * PP + n0 + bCc);
            cp16(dst, src);
        }
        cp_commit();
    };

    float acc[2][8][4];
#pragma unroll
    for (int mi = 0; mi < 2; mi++)
#pragma unroll
        for (int ni = 0; ni < 8; ni++)
#pragma unroll
            for (int r = 0; r < 4; r++) acc[mi][ni][r] = 0.f;

    const int KT = K / BK;
    issue(0);
    if (KT > 1) issue(1);

    for (int kt = 0; kt < KT; kt++) {
        if (kt + 1 < KT) { asm volatile("cp.async.wait_group 1;\n" ::: "memory"); }
        else             { asm volatile("cp.async.wait_group 0;\n" ::: "memory"); }
        __syncthreads();
        if (kt + 2 < KT) issue(kt + 2);

        const float* As = sm + (kt % KSTAGES) * STAGE_WORDS;
        const float* Bs = As + A_WORDS;
        const int k0 = kt * BK;

#pragma unroll
        for (int kk = 0; kk < 4; kk++) {
            const int kb = kk * 8;
            uint32_t a[2][4];
#pragma unroll
            for (int mi = 0; mi < 2; mi++) {
                int m = wm * 32 + mi * 16 + g;
                a[mi][0] = f2tf32(As[m * AS_STRIDE + kb + tig]);
                a[mi][1] = f2tf32(As[(m + 8) * AS_STRIDE + kb + tig]);
                a[mi][2] = f2tf32(As[m * AS_STRIDE + kb + tig + 4]);
                a[mi][3] = f2tf32(As[(m + 8) * AS_STRIDE + kb + tig + 4]);
            }
            uint32_t b[8][2];
            if (!GATE) {
#pragma unroll
                for (int ni = 0; ni < 8; ni++) {
                    int n = wn * 64 + ni * 8 + g;
                    b[ni][0] = f2tf32(Bs[(kb + tig) * BS_STRIDE + n]);
                    b[ni][1] = f2tf32(Bs[(kb + tig + 4) * BS_STRIDE + n]);
                }
            } else {
                int kr0 = k0 + kb + tig, kr1 = kr0 + 4;
                float cs0 = (kr0 >= C2C) ? cs_s[kr0 - C2C] : 0.f;
                float cs1 = (kr1 >= C2C) ? cs_s[kr1 - C2C] : 0.f;
#pragma unroll
                for (int ni = 0; ni < 8; ni++) {
                    int n = wn * 64 + ni * 8 + g;
                    float s0 = (kr0 < C2C) ? ss_s[n] : cs0;
                    float s1 = (kr1 < C2C) ? ss_s[n] : cs1;
                    b[ni][0] = f2tf32(Bs[(kb + tig) * BS_STRIDE + n] * s0);
                    b[ni][1] = f2tf32(Bs[(kb + tig + 4) * BS_STRIDE + n] * s1);
                }
            }
#pragma unroll
            for (int mi = 0; mi < 2; mi++)
#pragma unroll
                for (int ni = 0; ni < 8; ni++)
                    mma_tf32(acc[mi][ni], a[mi], b[ni]);
        }
    }

#pragma unroll
    for (int mi = 0; mi < 2; mi++) {
        int row_lo = m0 + wm * 32 + mi * 16 + g;
        int row_hi = row_lo + 8;
        float blo = (row_lo < M) ? bias[row_lo] : 0.f;
        float bhi = (row_hi < M) ? bias[row_hi] : 0.f;
#pragma unroll
        for (int ni = 0; ni < 8; ni++) {
            int col = n0 + wn * 64 + ni * 8 + tig * 2;
            float v0 = acc[mi][ni][0] + blo, v1 = acc[mi][ni][1] + blo;
            float v2 = acc[mi][ni][2] + bhi, v3 = acc[mi][ni][3] + bhi;
            if (ACT == 1) { v0 = fmaxf(v0, 0.f); v1 = fmaxf(v1, 0.f);
                            v2 = fmaxf(v2, 0.f); v3 = fmaxf(v3, 0.f); }
            if (ACT == 2) { v0 = tanhf(v0); v1 = tanhf(v1);
                            v2 = tanhf(v2); v3 = tanhf(v3); }
            if (row_lo < M) *(float2*)(Cp + (size_t)row_lo * N + col) = make_float2(v0, v1);
            if (row_hi < M) *(float2*)(Cp + (size_t)row_hi * N + col) = make_float2(v2, v3);
        }
    }
}

// ---------------- conv-fused GEMM v3: C = tanh(A * dwconv(X) + bias) ------------
// 512 threads, 64M x 128N tile (16 warps as 4m x 4n, 16x32 warp tiles).
// B[r][n] = 7-tap depthwise conv (DIR=1 horiz, DIR=2 vert) of X channel r + cb[r].
// TBN = 128 = exactly one image row.
template<int DIR>
__global__ __launch_bounds__(512) void gemm_conv(
    const float* __restrict__ A, const float* __restrict__ bias,
    const float* __restrict__ X, size_t sX,
    const float* __restrict__ w7, const float* __restrict__ cb,
    float* __restrict__ Cm, int M, int K, int N, size_t sC)
{
    extern __shared__ float sm[];
    float* AsB[2] = { sm, sm + CB_STAGE };

    const int bz = blockIdx.z;
    const float* Xp = X + (size_t)bz * sX;
    float*       Cp = Cm + (size_t)bz * sC;

    const int n0 = blockIdx.x * CB_N;           // one image row per block
    const int tid  = threadIdx.x;
    const int lane = tid & 31, warp = tid >> 5;
    const int wm = warp & 3, wn = warp >> 2;     // 4m x 4n, warp tile 16x32
    const int g = lane >> 2, tig = lane & 3;

    const int aRow = tid >> 3, aCc = (tid & 7) << 2;   // 1 pass of 64 rows
    const int bRow = tid >> 5, bCc = (tid & 31) << 2;  // 2 passes of 16 rows

    float4 ra, rb[2];

    auto loadA = [&](int k0) {
        ra = (aRow < M) ? *(const float4*)(A + (size_t)aRow * K + k0 + aCc)
                        : make_float4(0.f, 0.f, 0.f, 0.f);
    };
    auto loadB = [&](int k0) {
#pragma unroll
        for (int i = 0; i < 2; i++) {
            int c = k0 + bRow + i * 16;         // channel (k index)
            float bb = cb[c];
            const float* wc = w7 + c * 7;
            float o[4];
            if (DIR == 1) {
                int w4 = bCc;                    // pixel-in-row
                const float* xr = Xp + (size_t)c * PP + n0;
                float v[10];
                load_win10(xr, w4, v);
#pragma unroll
                for (int jj = 0; jj < 4; jj++) {
                    float s = bb;
#pragma unroll
                    for (int t = 0; t < 7; t++) s = fmaf(v[jj + t], wc[t], s);
                    o[jj] = s;
                }
            } else {
                int h = n0 >> 7;                 // constant per block
                const float* xb = Xp + (size_t)c * PP + bCc;
                float4 vt[7];
#pragma unroll
                for (int t = 0; t < 7; t++) {
                    int hh = h - 3 + t;
                    vt[t] = (hh >= 0 && hh < HH) ? *(const float4*)(xb + hh * WW)
                                                 : make_float4(0.f, 0.f, 0.f, 0.f);
                }
                float s0 = bb, s1 = bb, s2 = bb, s3 = bb;
#pragma unroll
                for (int t = 0; t < 7; t++) {
                    float wv = wc[t];
                    s0 = fmaf(vt[t].x, wv, s0);
                    s1 = fmaf(vt[t].y, wv, s1);
                    s2 = fmaf(vt[t].z, wv, s2);
                    s3 = fmaf(vt[t].w, wv, s3);
                }
                o[0] = s0; o[1] = s1; o[2] = s2; o[3] = s3;
            }
            rb[i] = make_float4(o[0], o[1], o[2], o[3]);
        }
    };
    auto stsAB = [&](int buf) {
        float* As = AsB[buf];
        float* Bs = As + CB_AW;
        *(float4*)&As[aRow * AS_STRIDE + aCc] = ra;
#pragma unroll
        for (int i = 0; i < 2; i++)
            *(float4*)&Bs[(bRow + i * 16) * CB_BSTR + bCc] = rb[i];
    };

    float acc[4][4];
#pragma unroll
    for (int ni = 0; ni < 4; ni++)
#pragma unroll
        for (int r = 0; r < 4; r++) acc[ni][r] = 0.f;

    const int KT = K / BK;
    loadA(0); loadB(0);
    stsAB(0);
    __syncthreads();

    int buf = 0;
    for (int kt = 0;;) {
        const int knext = kt + 1;
        if (knext < KT) { loadA(knext * BK); loadB(knext * BK); }

        const float* As = AsB[buf];
        const float* Bs = As + CB_AW;
#pragma unroll
        for (int kk = 0; kk < 4; kk++) {
            const int kb = kk * 8;
            uint32_t a[4];
            {
                int m = wm * 16 + g;
                a[0] = f2tf32(As[m * AS_STRIDE + kb + tig]);
                a[1] = f2tf32(As[(m + 8) * AS_STRIDE + kb + tig]);
                a[2] = f2tf32(As[m * AS_STRIDE + kb + tig + 4]);
                a[3] = f2tf32(As[(m + 8) * AS_STRIDE + kb + tig + 4]);
            }
            uint32_t b[4][2];
#pragma unroll
            for (int ni = 0; ni < 4; ni++) {
                int n = wn * 32 + ni * 8 + g;
                b[ni][0] = f2tf32(Bs[(kb + tig) * CB_BSTR + n]);
                b[ni][1] = f2tf32(Bs[(kb + tig + 4) * CB_BSTR + n]);
            }
#pragma unroll
            for (int ni = 0; ni < 4; ni++)
                mma_tf32(acc[ni], a, b[ni]);
        }

        if (knext >= KT) break;
        stsAB(buf ^ 1);
        __syncthreads();
        buf ^= 1;
        kt = knext;
    }

    {
        int row_lo = wm * 16 + g;
        int row_hi = row_lo + 8;
        float blo = (row_lo < M) ? bias[row_lo] : 0.f;
        float bhi = (row_hi < M) ? bias[row_hi] : 0.f;
#pragma unroll
        for (int ni = 0; ni < 4; ni++) {
            int col = n0 + wn * 32 + ni * 8 + tig * 2;
            float v0 = tanhf(acc[ni][0] + blo), v1 = tanhf(acc[ni][1] + blo);
            float v2 = tanhf(acc[ni][2] + bhi), v3 = tanhf(acc[ni][3] + bhi);
            if (row_lo < M) *(float2*)(Cp + (size_t)row_lo * N + col) = make_float2(v0, v1);
            if (row_hi < M) *(float2*)(Cp + (size_t)row_hi * N + col) = make_float2(v2, v3);
        }
    }
}

// ---------------- FSA horizontal, 4 outputs/thread -----------------------------
__global__ void fsa_h4(const float* __restrict__ x, size_t sX,
                       const float* __restrict__ kern, float* __restrict__ out)
{
    int idx = blockIdx.x * 256 + threadIdx.x;
    if (idx >= NB * C2C * HH * (WW / 4)) return;
    int w4 = (idx & 31) << 2;
    int row = idx >> 5;
    int h = row % HH, c = (row / HH) % C2C, b = row / (HH * C2C);
    const float* xr = x + (size_t)b * sX + (size_t)c * PP + h * WW;
    float v[10];
    load_win10(xr, w4, v);
    const float* kb_ = kern + ((size_t)b * GKC + (size_t)(c >> 4) * 5) * PP + h * WW + w4;
    float4 k0 = *(const float4*)(kb_);
    float4 k1 = *(const float4*)(kb_ + PP);
    float4 k2 = *(const float4*)(kb_ + 2 * PP);
    float4 k3 = *(const float4*)(kb_ + 3 * PP);
    float4 k4 = *(const float4*)(kb_ + 4 * PP);
    float K0[4] = {k0.x, k0.y, k0.z, k0.w};
    float K1[4] = {k1.x, k1.y, k1.z, k1.w};
    float K2[4] = {k2.x, k2.y, k2.z, k2.w};
    float K3[4] = {k3.x, k3.y, k3.z, k3.w};
    float K4[4] = {k4.x, k4.y, k4.z, k4.w};
    float o[4];
#pragma unroll
    for (int i = 0; i < 4; i++) {
        float t0 = (v[i] + v[i + 1]) * 0.5f;
        float t4 = (v[i + 5] + v[i + 6]) * 0.5f;
        float s = t0 * K0[i];
        s = fmaf(v[i + 2], K1[i], s);
        s = fmaf(v[i + 3], K2[i], s);
        s = fmaf(v[i + 4], K3[i], s);
        s = fmaf(t4, K4[i], s);
        o[i] = s;
    }
    *(float4*)(out + ((size_t)b * C2C + c) * PP + h * WW + w4) = make_float4(o[0], o[1], o[2], o[3]);
}

// ---------------- FSA vertical, 4 outputs/thread --------------------------------
__global__ void fsa_v4(const float* __restrict__ x, size_t sX,
                       const float* __restrict__ kern, float* __restrict__ out)
{
    int idx = blockIdx.x * 256 + threadIdx.x;
    if (idx >= NB * C2C * (HH / 4) * WW) return;
    int w = idx % WW;
    int h4 = ((idx / WW) & 31) << 2;
    int c = (idx / (WW * 32)) % C2C;
    int b = idx / (WW * 32 * C2C);
    const float* xc = x + (size_t)b * sX + (size_t)c * PP;
    float v[10];
#pragma unroll
    for (int t = 0; t < 10; t++) {
        int hi = h4 - 3 + t;
        v[t] = (hi >= 0 && hi < HH) ? xc[hi * WW + w] : 0.f;
    }
    const float* kb_ = kern + ((size_t)b * GKC + (size_t)(c >> 4) * 5) * PP + h4 * WW + w;
    float* ob = out + ((size_t)b * C2C + c) * PP + h4 * WW + w;
#pragma unroll
    for (int i = 0; i < 4; i++) {
        float t0 = (v[i] + v[i + 1]) * 0.5f;
        float t4 = (v[i + 5] + v[i + 6]) * 0.5f;
        float s = t0 * kb_[i * WW];
        s = fmaf(v[i + 2], kb_[PP + i * WW], s);
        s = fmaf(v[i + 3], kb_[2 * PP + i * WW], s);
        s = fmaf(v[i + 4], kb_[3 * PP + i * WW], s);
        s = fmaf(t4, kb_[4 * PP + i * WW], s);
        ob[i * WW] = s;
    }
}

// ---------------- reductions / gating -------------------------------------------
__global__ void reduce_mean_p(const float* __restrict__ x, float* __restrict__ out)
{
    int bc = blockIdx.x;
    const float* xr = x + (size_t)bc * PP;
    float s = 0.f;
    for (int i = threadIdx.x; i < PP; i += 256) s += xr[i];
    __shared__ float sm[256];
    sm[threadIdx.x] = s; __syncthreads();
    for (int st = 128; st > 0; st >>= 1) {
        if (threadIdx.x < st) sm[threadIdx.x] += sm[threadIdx.x + st];
        __syncthreads();
    }
    if (threadIdx.x == 0) out[bc] = sm[0] * (1.f / PP);
}

__global__ void ssig_xcmean(const float* __restrict__ xconv,
                            const float* __restrict__ atmean,
                            float* __restrict__ ssig, float* __restrict__ xcm)
{
    int b = blockIdx.y;
    int p = blockIdx.x * 256 + threadIdx.x;
    __shared__ float am[C2C];
    if (threadIdx.x < C2C) am[threadIdx.x] = atmean[b * C2C + threadIdx.x];
    __syncthreads();
    const float* xr = xconv + (size_t)b * C2C * PP + p;
    float s = 0.f, m = 0.f;
#pragma unroll 8
    for (int c = 0; c < C2C; c++) {
        float v = xr[(size_t)c * PP];
        s = fmaf(am[c], v, s);
        m += v;
    }
    s *= (1.f / C2C);
    ssig[b * PP + p] = 1.f / (1.f + expf(-s));
    xcm[b * PP + p] = m * (1.f / C2C);
}

__global__ void csig_kernel(const float* __restrict__ attn,
                            const float* __restrict__ xcmean,
                            float* __restrict__ out)
{
    int bc = blockIdx.x;
    int b = bc / C2C;
    const float* ar = attn + (size_t)bc * PP;
    const float* xm = xcmean + (size_t)b * PP;
    float s = 0.f;
    for (int i = threadIdx.x; i < PP; i += 256) s = fmaf(ar[i], xm[i], s);
    __shared__ float sm[256];
    sm[threadIdx.x] = s; __syncthreads();
    for (int st = 128; st > 0; st >>= 1) {
        if (threadIdx.x < st) sm[threadIdx.x] += sm[threadIdx.x + st];
        __syncthreads();
    }
    if (threadIdx.x == 0) {
        float v = sm[0] * (1.f / PP);
        out[bc] = 1.f / (1.f + expf(-v));
    }
}

// ---------------- host orchestration --------------------------------------------
extern "C" void kernel_launch(void* const* d_in, const int* in_sizes, int n_in,
                              void* d_out, int out_size)
{
    const float* x         = (const float*)d_in[0];
    const float* proj_in_w = (const float*)d_in[1];
    const float* proj_in_b = (const float*)d_in[2];
    const float* hk_dw_w   = (const float*)d_in[3];
    const float* hk_dw_b   = (const float*)d_in[4];
    const float* hk_pw_w   = (const float*)d_in[5];
    const float* hk_pw_b   = (const float*)d_in[6];
    const float* vk_dw_w   = (const float*)d_in[7];
    const float* vk_dw_b   = (const float*)d_in[8];
    const float* vk_pw_w   = (const float*)d_in[9];
    const float* vk_pw_b   = (const float*)d_in[10];
    const float* cb_w1     = (const float*)d_in[11];
    const float* cb_b1     = (const float*)d_in[12];
    const float* cb_w2     = (const float*)d_in[13];
    const float* cb_b2     = (const float*)d_in[14];
    const float* proj_out_w= (const float*)d_in[15];
    const float* proj_out_b= (const float*)d_in[16];
    float* out = (float*)d_out;

    static int smem_set = 0;
    if (!smem_set) {
        cudaFuncSetAttribute(gemm_tc<0,0,8>, cudaFuncAttributeMaxDynamicSharedMemorySize, GSMEM_BYTES);
        cudaFuncSetAttribute(gemm_tc<0,1,8>, cudaFuncAttributeMaxDynamicSharedMemorySize, GSMEM_BYTES);
        cudaFuncSetAttribute(gemm_tc<0,0,4>, cudaFuncAttributeMaxDynamicSharedMemorySize, GSMEM_BYTES);
        cudaFuncSetAttribute(gemm_tc<1,0,4>, cudaFuncAttributeMaxDynamicSharedMemorySize, GSMEM_BYTES);
        cudaFuncSetAttribute(gemm_conv<1>,   cudaFuncAttributeMaxDynamicSharedMemorySize, CBSMEM_BYTES);
        cudaFuncSetAttribute(gemm_conv<2>,   cudaFuncAttributeMaxDynamicSharedMemorySize, CBSMEM_BYTES);
        smem_set = 1;
    }

    float *p_h, *p_mid, *p_xconv, *p_k, *p_attnh, *p_attn;
    float *p_atmean, *p_xcmean, *p_ssig, *p_csig;
    cudaGetSymbolAddress((void**)&p_h,      g_h);
    cudaGetSymbolAddress((void**)&p_mid,    g_mid);
    cudaGetSymbolAddress((void**)&p_xconv,  g_xconv);
    cudaGetSymbolAddress((void**)&p_k,      g_k);
    cudaGetSymbolAddress((void**)&p_attnh,  g_attnh);
    cudaGetSymbolAddress((void**)&p_attn,   g_attn);
    cudaGetSymbolAddress((void**)&p_atmean, g_atmean);
    cudaGetSymbolAddress((void**)&p_xcmean, g_xcmean);
    cudaGetSymbolAddress((void**)&p_ssig,   g_ssig);
    cudaGetSymbolAddress((void**)&p_csig,   g_csig);

    const int N = PP;
    const int eb4 = (NB * C2C * PP / 4) / 256;

    // 1) proj_in (M=256,K=256) — BIG tile
    gemm_tc<0,0,8><<<dim3(N/128, 1, NB), 512, GSMEM_BYTES>>>(proj_in_w, proj_in_b, x, p_h,
        256, 256, N, (size_t)256*PP, (size_t)256*PP, nullptr, nullptr, nullptr);
    // 2) cb hidden = relu (M=64,K=128) — SMALL tile
    gemm_tc<1,0,4><<<dim3(N/256, 1, NB), 512, GSMEM_BYTES>>>(cb_w1, cb_b1, p_h, p_mid,
        64, 128, N, (size_t)256*PP, (size_t)64*PP, nullptr, nullptr, nullptr);
    // 3) x_conv (M=128,K=64) — SMALL tile
    gemm_tc<0,0,4><<<dim3(N/256, 1, NB), 512, GSMEM_BYTES>>>(cb_w2, cb_b2, p_mid, p_xconv,
        128, 64, N, (size_t)64*PP, (size_t)C2C*PP, nullptr, nullptr, nullptr);
    // 4+5) kh = tanh(hk_pw · dwconv_h(x2)) — conv-fused, 512 threads
    gemm_conv<1><<<dim3(N/CB_N, 1, NB), 512, CBSMEM_BYTES>>>(hk_pw_w, hk_pw_b,
        p_h + (size_t)C2C*PP, (size_t)256*PP, hk_dw_w, hk_dw_b, p_k,
        GKC, 128, N, (size_t)GKC*PP);
    // 6) attn_h
    fsa_h4<<<eb4, 256>>>(p_h + (size_t)C2C*PP, (size_t)256*PP, p_k, p_attnh);
    // 7+8) kv = tanh(vk_pw · dwconv_v(attn_h)) — conv-fused, 512 threads
    gemm_conv<2><<<dim3(N/CB_N, 1, NB), 512, CBSMEM_BYTES>>>(vk_pw_w, vk_pw_b,
        p_attnh, (size_t)C2C*PP, vk_dw_w, vk_dw_b, p_k,
        GKC, 128, N, (size_t)GKC*PP);
    // 9) attn
    fsa_v4<<<eb4, 256>>>(p_attnh, (size_t)C2C*PP, p_k, p_attn);
    // 10) at_mean
    reduce_mean_p<<<NB*C2C, 256>>>(p_attn, p_atmean);
    // 11) fused ssig + xcmean
    ssig_xcmean<<<dim3(PP/256, NB), 256>>>(p_xconv, p_atmean, p_ssig, p_xcmean);
    // 12) c_sig
    csig_kernel<<<NB*C2C, 256>>>(p_attn, p_xcmean, p_csig);
    // 13) proj_out with fused gating/concat (M=256,K=256) — BIG tile
    gemm_tc<0,1,8><<<dim3(N/128, 1, NB), 512, GSMEM_BYTES>>>(proj_out_w, proj_out_b, p_xconv, out,
        256, 256, N, (size_t)C2C*PP, (size_t)256*PP, p_attn, p_ssig, p_csig);
}

// round 13
// speedup vs baseline: 1.0912x; 1.0124x over previous
#include <cuda_runtime.h>
#include <math.h>
#include <stdint.h>

#define NB 4
#define C2C 128
#define HH 128
#define WW 128
#define PP (HH*WW)          // 16384
#define GKC 40

#define BK 32
#define AS_STRIDE 36
#define KSTAGES 3
#define MAX_STAGE_WORDS 13568
#define GSMEM_WORDS (KSTAGES*MAX_STAGE_WORDS + 384)
#define GSMEM_BYTES (GSMEM_WORDS*4)       // 164352

// conv-GEMM (vertical, register-staged): 64M x 128N tile, 512 threads
#define CB_M 64
#define CB_N 128
#define CB_BSTR 136
#define CB_AW (CB_M*AS_STRIDE)            // 2304
#define CB_BW (BK*CB_BSTR)                // 4352
#define CB_STAGE (CB_AW+CB_BW)            // 6656
#define CBSMEM_BYTES (2*CB_STAGE*4)       // 53248

// conv-GEMM horizontal v4 (cp.async staged raw X + smem conv pass)
#define CH_AW 2304                         // 64*36
#define CH_XSTR 132
#define CH_XW (32*CH_XSTR)                 // 4224
#define CH_BSTR 136
#define CH_BW (32*CH_BSTR)                 // 4352
#define CH_X_OFF (3*CH_AW)                 // 6912
#define CH_B_OFF (CH_X_OFF + 3*CH_XW)      // 19584
#define CHSMEM_WORDS (CH_B_OFF + 2*CH_BW)  // 28288
#define CHSMEM_BYTES (CHSMEM_WORDS*4)      // 113152

// ---------------- scratch -----------------------------------------------------
__device__ float g_h[(size_t)NB*256*PP];
__device__ float g_mid[(size_t)NB*64*PP];
__device__ float g_xconv[(size_t)NB*C2C*PP];
__device__ float g_k[(size_t)NB*GKC*PP];
__device__ float g_attnh[(size_t)NB*C2C*PP];
__device__ float g_attn[(size_t)NB*C2C*PP];
__device__ float g_atmean[NB*C2C];
__device__ float g_xcmean[NB*PP];
__device__ float g_ssig[NB*PP];
__device__ float g_csig[NB*C2C];

// ---------------- tf32 / cp.async helpers --------------------------------------
__device__ __forceinline__ uint32_t f2tf32(float x) {
    uint32_t u;
    asm("cvt.rna.tf32.f32 %0, %1;" : "=r"(u) : "f"(x));
    return u;
}
__device__ __forceinline__ void mma_tf32(float c[4], const uint32_t a[4], const uint32_t b[2]) {
    asm volatile(
        "mma.sync.aligned.m16n8k8.row.col.f32.tf32.tf32.f32 "
        "{%0,%1,%2,%3}, {%4,%5,%6,%7}, {%8,%9}, {%0,%1,%2,%3};\n"
        : "+f"(c[0]), "+f"(c[1]), "+f"(c[2]), "+f"(c[3])
        : "r"(a[0]), "r"(a[1]), "r"(a[2]), "r"(a[3]), "r"(b[0]), "r"(b[1]));
}
__device__ __forceinline__ void cp16(uint32_t dst, const void* src) {
    asm volatile("cp.async.cg.shared.global [%0], [%1], 16;\n"
                 :: "r"(dst), "l"(src) : "memory");
}
__device__ __forceinline__ void cp16_sz(uint32_t dst, const void* src, int sz) {
    asm volatile("cp.async.cg.shared.global [%0], [%1], 16, %2;\n"
                 :: "r"(dst), "l"(src), "r"(sz) : "memory");
}
__device__ __forceinline__ void cp_commit() {
    asm volatile("cp.async.commit_group;\n" ::: "memory");
}

// ---------------- window loader (horizontal, 10 taps around w4) ---------------
__device__ __forceinline__ void load_win10(const float* __restrict__ xr, int w4, float v[10]) {
    if (w4 >= 4 && w4 + 8 <= WW) {
        float4 A = *(const float4*)(xr + w4 - 4);
        float4 Bv = *(const float4*)(xr + w4);
        float4 Cv = *(const float4*)(xr + w4 + 4);
        v[0] = A.y;  v[1] = A.z;  v[2] = A.w;
        v[3] = Bv.x; v[4] = Bv.y; v[5] = Bv.z; v[6] = Bv.w;
        v[7] = Cv.x; v[8] = Cv.y; v[9] = Cv.z;
    } else {
#pragma unroll
        for (int t = 0; t < 10; t++) {
            int wi = w4 - 3 + t;
            v[t] = (wi >= 0 && wi < WW) ? xr[wi] : 0.f;
        }
    }
}

// ---------------- tf32 GEMM v6 (unchanged — best known) -------------------------
template<int ACT, int GATE, int WM>
__global__ __launch_bounds__(512) void gemm_tc(
    const float* __restrict__ A, const float* __restrict__ bias,
    const float* __restrict__ Bm, float* __restrict__ Cm,
    int M, int K, int N, size_t sB, size_t sC,
    const float* __restrict__ gAtt, const float* __restrict__ gSs,
    const float* __restrict__ gCs)
{
    constexpr int WN = 16 / WM;
    constexpr int TBM = WM * 32;
    constexpr int TBN = WN * 64;
    constexpr int BS_STRIDE = TBN + 8;
    constexpr int A_WORDS = TBM * AS_STRIDE;
    constexpr int B_WORDS = BK * BS_STRIDE;
    constexpr int STAGE_WORDS = A_WORDS + B_WORDS;
    constexpr int A_PASSES = TBM / 64;
    constexpr int B_PASSES = TBN / 64;
    constexpr int B_ROWS_PER_PASS = 2048 / TBN;

    extern __shared__ float sm[];
    float* ss_s = sm + KSTAGES * STAGE_WORDS;
    float* cs_s = ss_s + TBN;

    const int bz = blockIdx.z;
    const float* Bp = Bm + (size_t)bz * sB;
    float*       Cp = Cm + (size_t)bz * sC;
    const float* attB = GATE ? (gAtt + (size_t)bz * C2C * PP) : nullptr;

    const int m0 = blockIdx.y * TBM, n0 = blockIdx.x * TBN;
    const int tid  = threadIdx.x;
    const int lane = tid & 31, warp = tid >> 5;
    const int wm = warp % WM, wn = warp / WM;
    const int g = lane >> 2, tig = lane & 3;

    const int aRow = tid >> 3, aCc = (tid & 7) << 2;
    const int bRow = tid / (TBN / 4), bCc = (tid % (TBN / 4)) << 2;

    if (GATE) {
        if (tid < TBN)            ss_s[tid] = gSs[(size_t)bz * PP + n0 + tid];
        else if (tid < TBN + 128) cs_s[tid - TBN] = gCs[(size_t)bz * C2C + tid - TBN];
    }

    auto issue = [&](int kt) {
        const int k0 = kt * BK;
        float* As = sm + (kt % KSTAGES) * STAGE_WORDS;
        float* Bs = As + A_WORDS;
#pragma unroll
        for (int i = 0; i < A_PASSES; i++) {
            int r = aRow + i * 64;
            uint32_t dst = (uint32_t)__cvta_generic_to_shared(As + r * AS_STRIDE + aCc);
            const float* src = A + (size_t)(m0 + r) * K + k0 + aCc;
            cp16_sz(dst, src, (m0 + r < M) ? 16 : 0);
        }
#pragma unroll
        for (int i = 0; i < B_PASSES; i++) {
            int rr = bRow + i * B_ROWS_PER_PASS;
            int r = k0 + rr;
            uint32_t dst = (uint32_t)__cvta_generic_to_shared(Bs + rr * BS_STRIDE + bCc);
            const float* src;
            if (!GATE) src = Bp + (size_t)r * N + n0 + bCc;
            else       src = (r < C2C) ? (Bp + (size_t)r * PP + n0 + bCc)
                                       : (attB + (size_t)(r - C2C) * PP + n0 + bCc);
            cp16(dst, src);
        }
        cp_commit();
    };

    float acc[2][8][4];
#pragma unroll
    for (int mi = 0; mi < 2; mi++)
#pragma unroll
        for (int ni = 0; ni < 8; ni++)
#pragma unroll
            for (int r = 0; r < 4; r++) acc[mi][ni][r] = 0.f;

    const int KT = K / BK;
    issue(0);
    if (KT > 1) issue(1);

    for (int kt = 0; kt < KT; kt++) {
        if (kt + 1 < KT) { asm volatile("cp.async.wait_group 1;\n" ::: "memory"); }
        else             { asm volatile("cp.async.wait_group 0;\n" ::: "memory"); }
        __syncthreads();
        if (kt + 2 < KT) issue(kt + 2);

        const float* As = sm + (kt % KSTAGES) * STAGE_WORDS;
        const float* Bs = As + A_WORDS;
        const int k0 = kt * BK;

#pragma unroll
        for (int kk = 0; kk < 4; kk++) {
            const int kb = kk * 8;
            uint32_t a[2][4];
#pragma unroll
            for (int mi = 0; mi < 2; mi++) {
                int m = wm * 32 + mi * 16 + g;
                a[mi][0] = f2tf32(As[m * AS_STRIDE + kb + tig]);
                a[mi][1] = f2tf32(As[(m + 8) * AS_STRIDE + kb + tig]);
                a[mi][2] = f2tf32(As[m * AS_STRIDE + kb + tig + 4]);
                a[mi][3] = f2tf32(As[(m + 8) * AS_STRIDE + kb + tig + 4]);
            }
            uint32_t b[8][2];
            if (!GATE) {
#pragma unroll
                for (int ni = 0; ni < 8; ni++) {
                    int n = wn * 64 + ni * 8 + g;
                    b[ni][0] = f2tf32(Bs[(kb + tig) * BS_STRIDE + n]);
                    b[ni][1] = f2tf32(Bs[(kb + tig + 4) * BS_STRIDE + n]);
                }
            } else {
                int kr0 = k0 + kb + tig, kr1 = kr0 + 4;
                float cs0 = (kr0 >= C2C) ? cs_s[kr0 - C2C] : 0.f;
                float cs1 = (kr1 >= C2C) ? cs_s[kr1 - C2C] : 0.f;
#pragma unroll
                for (int ni = 0; ni < 8; ni++) {
                    int n = wn * 64 + ni * 8 + g;
                    float s0 = (kr0 < C2C) ? ss_s[n] : cs0;
                    float s1 = (kr1 < C2C) ? ss_s[n] : cs1;
                    b[ni][0] = f2tf32(Bs[(kb + tig) * BS_STRIDE + n] * s0);
                    b[ni][1] = f2tf32(Bs[(kb + tig + 4) * BS_STRIDE + n] * s1);
                }
            }
#pragma unroll
            for (int mi = 0; mi < 2; mi++)
#pragma unroll
                for (int ni = 0; ni < 8; ni++)
                    mma_tf32(acc[mi][ni], a[mi], b[ni]);
        }
    }

#pragma unroll
    for (int mi = 0; mi < 2; mi++) {
        int row_lo = m0 + wm * 32 + mi * 16 + g;
        int row_hi = row_lo + 8;
        float blo = (row_lo < M) ? bias[row_lo] : 0.f;
        float bhi = (row_hi < M) ? bias[row_hi] : 0.f;
#pragma unroll
        for (int ni = 0; ni < 8; ni++) {
            int col = n0 + wn * 64 + ni * 8 + tig * 2;
            float v0 = acc[mi][ni][0] + blo, v1 = acc[mi][ni][1] + blo;
            float v2 = acc[mi][ni][2] + bhi, v3 = acc[mi][ni][3] + bhi;
            if (ACT == 1) { v0 = fmaxf(v0, 0.f); v1 = fmaxf(v1, 0.f);
                            v2 = fmaxf(v2, 0.f); v3 = fmaxf(v3, 0.f); }
            if (ACT == 2) { v0 = tanhf(v0); v1 = tanhf(v1);
                            v2 = tanhf(v2); v3 = tanhf(v3); }
            if (row_lo < M) *(float2*)(Cp + (size_t)row_lo * N + col) = make_float2(v0, v1);
            if (row_hi < M) *(float2*)(Cp + (size_t)row_hi * N + col) = make_float2(v2, v3);
        }
    }
}

// ---------------- conv-fused GEMM horizontal v4 ---------------------------------
// C = tanh(A * dwconv_h(X) + bias). 512 threads, 64M x 128N tile (16 warps,
// 4m x 4n, 16x32 warp tiles). Raw X rows staged via 3-stage cp.async; a smem
// conv pass builds the B tile (zero pad at image row boundary = block boundary).
__global__ __launch_bounds__(512) void gemm_conv_h(
    const float* __restrict__ A, const float* __restrict__ bias,
    const float* __restrict__ X, size_t sX,
    const float* __restrict__ w7, const float* __restrict__ cb,
    float* __restrict__ Cm, int M, int K, int N, size_t sC)
{
    extern __shared__ float sm[];

    const int bz = blockIdx.z;
    const float* Xp = X + (size_t)bz * sX;
    float*       Cp = Cm + (size_t)bz * sC;

    const int n0 = blockIdx.x * CB_N;            // one image row per block
    const int tid  = threadIdx.x;
    const int lane = tid & 31, warp = tid >> 5;
    const int wm = warp & 3, wn = warp >> 2;     // 4m x 4n, warp tile 16x32
    const int g = lane >> 2, tig = lane & 3;

    const int aRow = tid >> 3, aCc = (tid & 7) << 2;
    const int xCh  = tid >> 4, xPx = (tid & 15) << 3;   // 32 ch x 128 px, 8 px/thread

    auto issue = [&](int kt) {
        const int k0 = kt * BK;
        float* As = sm + (kt % 3) * CH_AW;
        float* Xs = sm + CH_X_OFF + (kt % 3) * CH_XW;
        uint32_t dstA = (uint32_t)__cvta_generic_to_shared(As + aRow * AS_STRIDE + aCc);
        cp16_sz(dstA, A + (size_t)aRow * K + k0 + aCc, (aRow < M) ? 16 : 0);
        const float* src = Xp + (size_t)(k0 + xCh) * PP + n0 + xPx;
        uint32_t dstX = (uint32_t)__cvta_generic_to_shared(Xs + xCh * CH_XSTR + xPx);
        cp16(dstX, src);
        cp16(dstX + 16, src + 4);
        cp_commit();
    };

    auto convpass = [&](int kt) {
        const int k0 = kt * BK;
        const float* Xs = sm + CH_X_OFF + (kt % 3) * CH_XW + xCh * CH_XSTR;
        float*       Bs = sm + CH_B_OFF + (kt & 1) * CH_BW + xCh * CH_BSTR;
        const float* wc = w7 + (size_t)(k0 + xCh) * 7;
        float bb = cb[k0 + xCh];
        float v[14];
#pragma unroll
        for (int t = 0; t < 14; t++) {
            int px = xPx - 3 + t;
            v[t] = (px >= 0 && px < WW) ? Xs[px] : 0.f;
        }
#pragma unroll
        for (int j = 0; j < 8; j++) {
            float s = bb;
#pragma unroll
            for (int t = 0; t < 7; t++) s = fmaf(v[j + t], wc[t], s);
            Bs[xPx + j] = s;
        }
    };

    float acc[4][4];
#pragma unroll
    for (int ni = 0; ni < 4; ni++)
#pragma unroll
        for (int r = 0; r < 4; r++) acc[ni][r] = 0.f;

    const int KT = K / BK;   // 4
    issue(0);
    issue(1);

    for (int kt = 0; kt < KT; kt++) {
        if (kt + 1 < KT) { asm volatile("cp.async.wait_group 1;\n" ::: "memory"); }
        else             { asm volatile("cp.async.wait_group 0;\n" ::: "memory"); }
        __syncthreads();
        convpass(kt);
        if (kt + 2 < KT) issue(kt + 2);
        __syncthreads();

        const float* As = sm + (kt % 3) * CH_AW;
        const float* Bs = sm + CH_B_OFF + (kt & 1) * CH_BW;
#pragma unroll
        for (int kk = 0; kk < 4; kk++) {
            const int kb = kk * 8;
            uint32_t a[4];
            {
                int m = wm * 16 + g;
                a[0] = f2tf32(As[m * AS_STRIDE + kb + tig]);
                a[1] = f2tf32(As[(m + 8) * AS_STRIDE + kb + tig]);
                a[2] = f2tf32(As[m * AS_STRIDE + kb + tig + 4]);
                a[3] = f2tf32(As[(m + 8) * AS_STRIDE + kb + tig + 4]);
            }
            uint32_t b[4][2];
#pragma unroll
            for (int ni = 0; ni < 4; ni++) {
                int n = wn * 32 + ni * 8 + g;
                b[ni][0] = f2tf32(Bs[(kb + tig) * CH_BSTR + n]);
                b[ni][1] = f2tf32(Bs[(kb + tig + 4) * CH_BSTR + n]);
            }
#pragma unroll
            for (int ni = 0; ni < 4; ni++)
                mma_tf32(acc[ni], a, b[ni]);
        }
    }

    {
        int row_lo = wm * 16 + g;
        int row_hi = row_lo + 8;
        float blo = (row_lo < M) ? bias[row_lo] : 0.f;
        float bhi = (row_hi < M) ? bias[row_hi] : 0.f;
#pragma unroll
        for (int ni = 0; ni < 4; ni++) {
            int col = n0 + wn * 32 + ni * 8 + tig * 2;
            float v0 = tanhf(acc[ni][0] + blo), v1 = tanhf(acc[ni][1] + blo);
            float v2 = tanhf(acc[ni][2] + bhi), v3 = tanhf(acc[ni][3] + bhi);
            if (row_lo < M) *(float2*)(Cp + (size_t)row_lo * N + col) = make_float2(v0, v1);
            if (row_hi < M) *(float2*)(Cp + (size_t)row_hi * N + col) = make_float2(v2, v3);
        }
    }
}

// ---------------- conv-fused GEMM vertical (register-staged, unchanged) ---------
__global__ __launch_bounds__(512) void gemm_conv_v(
    const float* __restrict__ A, const float* __restrict__ bias,
    const float* __restrict__ X, size_t sX,
    const float* __restrict__ w7, const float* __restrict__ cb,
    float* __restrict__ Cm, int M, int K, int N, size_t sC)
{
    extern __shared__ float sm[];
    float* AsB[2] = { sm, sm + CB_STAGE };

    const int bz = blockIdx.z;
    const float* Xp = X + (size_t)bz * sX;
    float*       Cp = Cm + (size_t)bz * sC;

    const int n0 = blockIdx.x * CB_N;
    const int tid  = threadIdx.x;
    const int lane = tid & 31, warp = tid >> 5;
    const int wm = warp & 3, wn = warp >> 2;
    const int g = lane >> 2, tig = lane & 3;

    const int aRow = tid >> 3, aCc = (tid & 7) << 2;
    const int bRow = tid >> 5, bCc = (tid & 31) << 2;

    float4 ra, rb[2];

    auto loadA = [&](int k0) {
        ra = (aRow < M) ? *(const float4*)(A + (size_t)aRow * K + k0 + aCc)
                        : make_float4(0.f, 0.f, 0.f, 0.f);
    };
    auto loadB = [&](int k0) {
#pragma unroll
        for (int i = 0; i < 2; i++) {
            int c = k0 + bRow + i * 16;
            float bb = cb[c];
            const float* wc = w7 + c * 7;
            int h = n0 >> 7;
            const float* xb = Xp + (size_t)c * PP + bCc;
            float4 vt[7];
#pragma unroll
            for (int t = 0; t < 7; t++) {
                int hh = h - 3 + t;
                vt[t] = (hh >= 0 && hh < HH) ? *(const float4*)(xb + hh * WW)
                                             : make_float4(0.f, 0.f, 0.f, 0.f);
            }
            float s0 = bb, s1 = bb, s2 = bb, s3 = bb;
#pragma unroll
            for (int t = 0; t < 7; t++) {
                float wv = wc[t];
                s0 = fmaf(vt[t].x, wv, s0);
                s1 = fmaf(vt[t].y, wv, s1);
                s2 = fmaf(vt[t].z, wv, s2);
                s3 = fmaf(vt[t].w, wv, s3);
            }
            rb[i] = make_float4(s0, s1, s2, s3);
        }
    };
    auto stsAB = [&](int buf) {
        float* As = AsB[buf];
        float* Bs = As + CB_AW;
        *(float4*)&As[aRow * AS_STRIDE + aCc] = ra;
#pragma unroll
        for (int i = 0; i < 2; i++)
            *(float4*)&Bs[(bRow + i * 16) * CB_BSTR + bCc] = rb[i];
    };

    float acc[4][4];
#pragma unroll
    for (int ni = 0; ni < 4; ni++)
#pragma unroll
        for (int r = 0; r < 4; r++) acc[ni][r] = 0.f;

    const int KT = K / BK;
    loadA(0); loadB(0);
    stsAB(0);
    __syncthreads();

    int buf = 0;
    for (int kt = 0;;) {
        const int knext = kt + 1;
        if (knext < KT) { loadA(knext * BK); loadB(knext * BK); }

        const float* As = AsB[buf];
        const float* Bs = As + CB_AW;
#pragma unroll
        for (int kk = 0; kk < 4; kk++) {
            const int kb = kk * 8;
            uint32_t a[4];
            {
                int m = wm * 16 + g;
                a[0] = f2tf32(As[m * AS_STRIDE + kb + tig]);
                a[1] = f2tf32(As[(m + 8) * AS_STRIDE + kb + tig]);
                a[2] = f2tf32(As[m * AS_STRIDE + kb + tig + 4]);
                a[3] = f2tf32(As[(m + 8) * AS_STRIDE + kb + tig + 4]);
            }
            uint32_t b[4][2];
#pragma unroll
            for (int ni = 0; ni < 4; ni++) {
                int n = wn * 32 + ni * 8 + g;
                b[ni][0] = f2tf32(Bs[(kb + tig) * CB_BSTR + n]);
                b[ni][1] = f2tf32(Bs[(kb + tig + 4) * CB_BSTR + n]);
            }
#pragma unroll
            for (int ni = 0; ni < 4; ni++)
                mma_tf32(acc[ni], a, b[ni]);
        }

        if (knext >= KT) break;
        stsAB(buf ^ 1);
        __syncthreads();
        buf ^= 1;
        kt = knext;
    }

    {
        int row_lo = wm * 16 + g;
        int row_hi = row_lo + 8;
        float blo = (row_lo < M) ? bias[row_lo] : 0.f;
        float bhi = (row_hi < M) ? bias[row_hi] : 0.f;
#pragma unroll
        for (int ni = 0; ni < 4; ni++) {
            int col = n0 + wn * 32 + ni * 8 + tig * 2;
            float v0 = tanhf(acc[ni][0] + blo), v1 = tanhf(acc[ni][1] + blo);
            float v2 = tanhf(acc[ni][2] + bhi), v3 = tanhf(acc[ni][3] + bhi);
            if (row_lo < M) *(float2*)(Cp + (size_t)row_lo * N + col) = make_float2(v0, v1);
            if (row_hi < M) *(float2*)(Cp + (size_t)row_hi * N + col) = make_float2(v2, v3);
        }
    }
}

// ---------------- FSA horizontal, 4 outputs/thread -----------------------------
__global__ void fsa_h4(const float* __restrict__ x, size_t sX,
                       const float* __restrict__ kern, float* __restrict__ out)
{
    int idx = blockIdx.x * 256 + threadIdx.x;
    if (idx >= NB * C2C * HH * (WW / 4)) return;
    int w4 = (idx & 31) << 2;
    int row = idx >> 5;
    int h = row % HH, c = (row / HH) % C2C, b = row / (HH * C2C);
    const float* xr = x + (size_t)b * sX + (size_t)c * PP + h * WW;
    float v[10];
    load_win10(xr, w4, v);
    const float* kb_ = kern + ((size_t)b * GKC + (size_t)(c >> 4) * 5) * PP + h * WW + w4;
    float4 k0 = *(const float4*)(kb_);
    float4 k1 = *(const float4*)(kb_ + PP);
    float4 k2 = *(const float4*)(kb_ + 2 * PP);
    float4 k3 = *(const float4*)(kb_ + 3 * PP);
    float4 k4 = *(const float4*)(kb_ + 4 * PP);
    float K0[4] = {k0.x, k0.y, k0.z, k0.w};
    float K1[4] = {k1.x, k1.y, k1.z, k1.w};
    float K2[4] = {k2.x, k2.y, k2.z, k2.w};
    float K3[4] = {k3.x, k3.y, k3.z, k3.w};
    float K4[4] = {k4.x, k4.y, k4.z, k4.w};
    float o[4];
#pragma unroll
    for (int i = 0; i < 4; i++) {
        float t0 = (v[i] + v[i + 1]) * 0.5f;
        float t4 = (v[i + 5] + v[i + 6]) * 0.5f;
        float s = t0 * K0[i];
        s = fmaf(v[i + 2], K1[i], s);
        s = fmaf(v[i + 3], K2[i], s);
        s = fmaf(v[i + 4], K3[i], s);
        s = fmaf(t4, K4[i], s);
        o[i] = s;
    }
    *(float4*)(out + ((size_t)b * C2C + c) * PP + h * WW + w4) = make_float4(o[0], o[1], o[2], o[3]);
}

// ---------------- FSA vertical, 4 outputs/thread --------------------------------
__global__ void fsa_v4(const float* __restrict__ x, size_t sX,
                       const float* __restrict__ kern, float* __restrict__ out)
{
    int idx = blockIdx.x * 256 + threadIdx.x;
    if (idx >= NB * C2C * (HH / 4) * WW) return;
    int w = idx % WW;
    int h4 = ((idx / WW) & 31) << 2;
    int c = (idx / (WW * 32)) % C2C;
    int b = idx / (WW * 32 * C2C);
    const float* xc = x + (size_t)b * sX + (size_t)c * PP;
    float v[10];
#pragma unroll
    for (int t = 0; t < 10; t++) {
        int hi = h4 - 3 + t;
        v[t] = (hi >= 0 && hi < HH) ? xc[hi * WW + w] : 0.f;
    }
    const float* kb_ = kern + ((size_t)b * GKC + (size_t)(c >> 4) * 5) * PP + h4 * WW + w;
    float* ob = out + ((size_t)b * C2C + c) * PP + h4 * WW + w;
#pragma unroll
    for (int i = 0; i < 4; i++) {
        float t0 = (v[i] + v[i + 1]) * 0.5f;
        float t4 = (v[i + 5] + v[i + 6]) * 0.5f;
        float s = t0 * kb_[i * WW];
        s = fmaf(v[i + 2], kb_[PP + i * WW], s);
        s = fmaf(v[i + 3], kb_[2 * PP + i * WW], s);
        s = fmaf(v[i + 4], kb_[3 * PP + i * WW], s);
        s = fmaf(t4, kb_[4 * PP + i * WW], s);
        ob[i * WW] = s;
    }
}

// ---------------- reductions / gating -------------------------------------------
__global__ void reduce_mean_p(const float* __restrict__ x, float* __restrict__ out)
{
    int bc = blockIdx.x;
    const float* xr = x + (size_t)bc * PP;
    float s = 0.f;
    for (int i = threadIdx.x; i < PP; i += 256) s += xr[i];
    __shared__ float sm[256];
    sm[threadIdx.x] = s; __syncthreads();
    for (int st = 128; st > 0; st >>= 1) {
        if (threadIdx.x < st) sm[threadIdx.x] += sm[threadIdx.x + st];
        __syncthreads();
    }
    if (threadIdx.x == 0) out[bc] = sm[0] * (1.f / PP);
}

__global__ void ssig_xcmean(const float* __restrict__ xconv,
                            const float* __restrict__ atmean,
                            float* __restrict__ ssig, float* __restrict__ xcm)
{
    int b = blockIdx.y;
    int p = blockIdx.x * 256 + threadIdx.x;
    __shared__ float am[C2C];
    if (threadIdx.x < C2C) am[threadIdx.x] = atmean[b * C2C + threadIdx.x];
    __syncthreads();
    const float* xr = xconv + (size_t)b * C2C * PP + p;
    float s = 0.f, m = 0.f;
#pragma unroll 8
    for (int c = 0; c < C2C; c++) {
        float v = xr[(size_t)c * PP];
        s = fmaf(am[c], v, s);
        m += v;
    }
    s *= (1.f / C2C);
    ssig[b * PP + p] = 1.f / (1.f + expf(-s));
    xcm[b * PP + p] = m * (1.f / C2C);
}

__global__ void csig_kernel(const float* __restrict__ attn,
                            const float* __restrict__ xcmean,
                            float* __restrict__ out)
{
    int bc = blockIdx.x;
    int b = bc / C2C;
    const float* ar = attn + (size_t)bc * PP;
    const float* xm = xcmean + (size_t)b * PP;
    float s = 0.f;
    for (int i = threadIdx.x; i < PP; i += 256) s = fmaf(ar[i], xm[i], s);
    __shared__ float sm[256];
    sm[threadIdx.x] = s; __syncthreads();
    for (int st = 128; st > 0; st >>= 1) {
        if (threadIdx.x < st) sm[threadIdx.x] += sm[threadIdx.x + st];
        __syncthreads();
    }
    if (threadIdx.x == 0) {
        float v = sm[0] * (1.f / PP);
        out[bc] = 1.f / (1.f + expf(-v));
    }
}

// ---------------- host orchestration --------------------------------------------
extern "C" void kernel_launch(void* const* d_in, const int* in_sizes, int n_in,
                              void* d_out, int out_size)
{
    const float* x         = (const float*)d_in[0];
    const float* proj_in_w = (const float*)d_in[1];
    const float* proj_in_b = (const float*)d_in[2];
    const float* hk_dw_w   = (const float*)d_in[3];
    const float* hk_dw_b   = (const float*)d_in[4];
    const float* hk_pw_w   = (const float*)d_in[5];
    const float* hk_pw_b   = (const float*)d_in[6];
    const float* vk_dw_w   = (const float*)d_in[7];
    const float* vk_dw_b   = (const float*)d_in[8];
    const float* vk_pw_w   = (const float*)d_in[9];
    const float* vk_pw_b   = (const float*)d_in[10];
    const float* cb_w1     = (const float*)d_in[11];
    const float* cb_b1     = (const float*)d_in[12];
    const float* cb_w2     = (const float*)d_in[13];
    const float* cb_b2     = (const float*)d_in[14];
    const float* proj_out_w= (const float*)d_in[15];
    const float* proj_out_b= (const float*)d_in[16];
    float* out = (float*)d_out;

    static int smem_set = 0;
    if (!smem_set) {
        cudaFuncSetAttribute(gemm_tc<0,0,8>, cudaFuncAttributeMaxDynamicSharedMemorySize, GSMEM_BYTES);
        cudaFuncSetAttribute(gemm_tc<0,1,8>, cudaFuncAttributeMaxDynamicSharedMemorySize, GSMEM_BYTES);
        cudaFuncSetAttribute(gemm_tc<0,0,4>, cudaFuncAttributeMaxDynamicSharedMemorySize, GSMEM_BYTES);
        cudaFuncSetAttribute(gemm_tc<1,0,4>, cudaFuncAttributeMaxDynamicSharedMemorySize, GSMEM_BYTES);
        cudaFuncSetAttribute(gemm_conv_h,    cudaFuncAttributeMaxDynamicSharedMemorySize, CHSMEM_BYTES);
        cudaFuncSetAttribute(gemm_conv_v,    cudaFuncAttributeMaxDynamicSharedMemorySize, CBSMEM_BYTES);
        smem_set = 1;
    }

    float *p_h, *p_mid, *p_xconv, *p_k, *p_attnh, *p_attn;
    float *p_atmean, *p_xcmean, *p_ssig, *p_csig;
    cudaGetSymbolAddress((void**)&p_h,      g_h);
    cudaGetSymbolAddress((void**)&p_mid,    g_mid);
    cudaGetSymbolAddress((void**)&p_xconv,  g_xconv);
    cudaGetSymbolAddress((void**)&p_k,      g_k);
    cudaGetSymbolAddress((void**)&p_attnh,  g_attnh);
    cudaGetSymbolAddress((void**)&p_attn,   g_attn);
    cudaGetSymbolAddress((void**)&p_atmean, g_atmean);
    cudaGetSymbolAddress((void**)&p_xcmean, g_xcmean);
    cudaGetSymbolAddress((void**)&p_ssig,   g_ssig);
    cudaGetSymbolAddress((void**)&p_csig,   g_csig);

    const int N = PP;
    const int eb4 = (NB * C2C * PP / 4) / 256;

    // 1) proj_in (M=256,K=256) — BIG tile
    gemm_tc<0,0,8><<<dim3(N/128, 1, NB), 512, GSMEM_BYTES>>>(proj_in_w, proj_in_b, x, p_h,
        256, 256, N, (size_t)256*PP, (size_t)256*PP, nullptr, nullptr, nullptr);
    // 2) cb hidden = relu (M=64,K=128) — SMALL tile
    gemm_tc<1,0,4><<<dim3(N/256, 1, NB), 512, GSMEM_BYTES>>>(cb_w1, cb_b1, p_h, p_mid,
        64, 128, N, (size_t)256*PP, (size_t)64*PP, nullptr, nullptr, nullptr);
    // 3) x_conv (M=128,K=64) — SMALL tile
    gemm_tc<0,0,4><<<dim3(N/256, 1, NB), 512, GSMEM_BYTES>>>(cb_w2, cb_b2, p_mid, p_xconv,
        128, 64, N, (size_t)64*PP, (size_t)C2C*PP, nullptr, nullptr, nullptr);
    // 4+5) kh = tanh(hk_pw · dwconv_h(x2)) — cp.async-staged conv GEMM
    gemm_conv_h<<<dim3(N/CB_N, 1, NB), 512, CHSMEM_BYTES>>>(hk_pw_w, hk_pw_b,
        p_h + (size_t)C2C*PP, (size_t)256*PP, hk_dw_w, hk_dw_b, p_k,
        GKC, 128, N, (size_t)GKC*PP);
    // 6) attn_h
    fsa_h4<<<eb4, 256>>>(p_h + (size_t)C2C*PP, (size_t)256*PP, p_k, p_attnh);
    // 7+8) kv = tanh(vk_pw · dwconv_v(attn_h)) — register-staged conv GEMM
    gemm_conv_v<<<dim3(N/CB_N, 1, NB), 512, CBSMEM_BYTES>>>(vk_pw_w, vk_pw_b,
        p_attnh, (size_t)C2C*PP, vk_dw_w, vk_dw_b, p_k,
        GKC, 128, N, (size_t)GKC*PP);
    // 9) attn
    fsa_v4<<<eb4, 256>>>(p_attnh, (size_t)C2C*PP, p_k, p_attn);
    // 10) at_mean
    reduce_mean_p<<<NB*C2C, 256>>>(p_attn, p_atmean);
    // 11) fused ssig + xcmean
    ssig_xcmean<<<dim3(PP/256, NB), 256>>>(p_xconv, p_atmean, p_ssig, p_xcmean);
    // 12) c_sig
    csig_kernel<<<NB*C2C, 256>>>(p_attn, p_xcmean, p_csig);
    // 13) proj_out with fused gating/concat (M=256,K=256) — BIG tile
    gemm_tc<0,1,8><<<dim3(N/128, 1, NB), 512, GSMEM_BYTES>>>(proj_out_w, proj_out_b, p_xconv, out,
        256, 256, N, (size_t)C2C*PP, (size_t)256*PP, p_attn, p_ssig, p_csig);
}

// round 14
// speedup vs baseline: 1.2118x; 1.1105x over previous
#include <cuda_runtime.h>
#include <math.h>
#include <stdint.h>

#define NB 4
#define C2C 128
#define HH 128
#define WW 128
#define PP (HH*WW)          // 16384
#define GKC 40

#define BK 32
#define AS_STRIDE 36

// gemm_tc256: 128M x 128N tile, 256 threads, 3-stage cp.async, 2 CTAs/SM
#define GT_AW (128*AS_STRIDE)              // 4608
#define GT_BSTR 136
#define GT_BW (BK*GT_BSTR)                 // 4352
#define GT_STAGE (GT_AW+GT_BW)             // 8960
#define GT_WORDS (3*GT_STAGE + 384)        // 27264+384
#define GT_BYTES (GT_WORDS*4)              // 110592 -> fits 2/SM

// conv-GEMM (vertical, register-staged): 64M x 128N tile, 512 threads
#define CB_M 64
#define CB_N 128
#define CB_BSTR 136
#define CB_AW (CB_M*AS_STRIDE)             // 2304
#define CB_BW (BK*CB_BSTR)                 // 4352
#define CB_STAGE (CB_AW+CB_BW)             // 6656
#define CBSMEM_BYTES (2*CB_STAGE*4)        // 53248

// conv-GEMM horizontal (cp.async staged raw X + smem conv pass)
#define CH_AW 2304                         // 64*36
#define CH_XSTR 132
#define CH_XW (32*CH_XSTR)                 // 4224
#define CH_BSTR 136
#define CH_BW (32*CH_BSTR)                 // 4352
#define CH_X_OFF (3*CH_AW)                 // 6912
#define CH_B_OFF (CH_X_OFF + 3*CH_XW)      // 19584
#define CHSMEM_WORDS (CH_B_OFF + 2*CH_BW)  // 28288
#define CHSMEM_BYTES (CHSMEM_WORDS*4)      // 113152

// ---------------- scratch -----------------------------------------------------
__device__ float g_h[(size_t)NB*256*PP];
__device__ float g_mid[(size_t)NB*64*PP];
__device__ float g_xconv[(size_t)NB*C2C*PP];
__device__ float g_k[(size_t)NB*GKC*PP];
__device__ float g_attnh[(size_t)NB*C2C*PP];
__device__ float g_attn[(size_t)NB*C2C*PP];
__device__ float g_atmean[NB*C2C];
__device__ float g_xcmean[NB*PP];
__device__ float g_ssig[NB*PP];
__device__ float g_csig[NB*C2C];

// ---------------- tf32 / cp.async helpers --------------------------------------
__device__ __forceinline__ uint32_t f2tf32(float x) {
    uint32_t u;
    asm("cvt.rna.tf32.f32 %0, %1;" : "=r"(u) : "f"(x));
    return u;
}
__device__ __forceinline__ void mma_tf32(float c[4], const uint32_t a[4], const uint32_t b[2]) {
    asm volatile(
        "mma.sync.aligned.m16n8k8.row.col.f32.tf32.tf32.f32 "
        "{%0,%1,%2,%3}, {%4,%5,%6,%7}, {%8,%9}, {%0,%1,%2,%3};\n"
        : "+f"(c[0]), "+f"(c[1]), "+f"(c[2]), "+f"(c[3])
        : "r"(a[0]), "r"(a[1]), "r"(a[2]), "r"(a[3]), "r"(b[0]), "r"(b[1]));
}
__device__ __forceinline__ void cp16(uint32_t dst, const void* src) {
    asm volatile("cp.async.cg.shared.global [%0], [%1], 16;\n"
                 :: "r"(dst), "l"(src) : "memory");
}
__device__ __forceinline__ void cp16_sz(uint32_t dst, const void* src, int sz) {
    asm volatile("cp.async.cg.shared.global [%0], [%1], 16, %2;\n"
                 :: "r"(dst), "l"(src), "r"(sz) : "memory");
}
__device__ __forceinline__ void cp_commit() {
    asm volatile("cp.async.commit_group;\n" ::: "memory");
}

// ---------------- window loader (horizontal, 10 taps around w4) ---------------
__device__ __forceinline__ void load_win10(const float* __restrict__ xr, int w4, float v[10]) {
    if (w4 >= 4 && w4 + 8 <= WW) {
        float4 A = *(const float4*)(xr + w4 - 4);
        float4 Bv = *(const float4*)(xr + w4);
        float4 Cv = *(const float4*)(xr + w4 + 4);
        v[0] = A.y;  v[1] = A.z;  v[2] = A.w;
        v[3] = Bv.x; v[4] = Bv.y; v[5] = Bv.z; v[6] = Bv.w;
        v[7] = Cv.x; v[8] = Cv.y; v[9] = Cv.z;
    } else {
#pragma unroll
        for (int t = 0; t < 10; t++) {
            int wi = w4 - 3 + t;
            v[t] = (wi >= 0 && wi < WW) ? xr[wi] : 0.f;
        }
    }
}

// ---------------- tf32 GEMM v7: 128x128 tile, 256 threads, 2 CTAs/SM -----------
// 8 warps as 4m x 2n, warp tile 32x64. 3-stage cp.async pipeline.
// GATE=1: B rows 0..127 = xconv*ssig[col], rows 128..255 = attn*csig[row].
template<int ACT, int GATE>
__global__ __launch_bounds__(256, 2) void gemm_tc256(
    const float* __restrict__ A, const float* __restrict__ bias,
    const float* __restrict__ Bm, float* __restrict__ Cm,
    int M, int K, int N, size_t sB, size_t sC,
    const float* __restrict__ gAtt, const float* __restrict__ gSs,
    const float* __restrict__ gCs)
{
    extern __shared__ float sm[];
    float* ss_s = sm + 3 * GT_STAGE;   // 128 col gates
    float* cs_s = ss_s + 128;           // 128 row gates

    const int bz = blockIdx.z;
    const float* Bp = Bm + (size_t)bz * sB;
    float*       Cp = Cm + (size_t)bz * sC;
    const float* attB = GATE ? (gAtt + (size_t)bz * C2C * PP) : nullptr;

    const int m0 = blockIdx.y * 128, n0 = blockIdx.x * 128;
    const int tid  = threadIdx.x;
    const int lane = tid & 31, warp = tid >> 5;
    const int wm = warp & 3, wn = warp >> 2;      // 4m x 2n
    const int g = lane >> 2, tig = lane & 3;

    const int aRow = tid >> 3, aCc = (tid & 7) << 2;   // 4 passes of 32 rows
    const int bRow = tid >> 5, bCc = (tid & 31) << 2;  // 4 passes of 8 rows

    if (GATE) {
        if (tid < 128)      ss_s[tid] = gSs[(size_t)bz * PP + n0 + tid];
        else                cs_s[tid - 128] = gCs[(size_t)bz * C2C + tid - 128];
    }

    auto issue = [&](int kt) {
        const int k0 = kt * BK;
        float* As = sm + (kt % 3) * GT_STAGE;
        float* Bs = As + GT_AW;
#pragma unroll
        for (int i = 0; i < 4; i++) {
            int r = aRow + i * 32;
            uint32_t dst = (uint32_t)__cvta_generic_to_shared(As + r * AS_STRIDE + aCc);
            const float* src = A + (size_t)(m0 + r) * K + k0 + aCc;
            cp16_sz(dst, src, (m0 + r < M) ? 16 : 0);
        }
#pragma unroll
        for (int i = 0; i < 4; i++) {
            int rr = bRow + i * 8;
            int r = k0 + rr;
            uint32_t dst = (uint32_t)__cvta_generic_to_shared(Bs + rr * GT_BSTR + bCc);
            const float* src;
            if (!GATE) src = Bp + (size_t)r * N + n0 + bCc;
            else       src = (r < C2C) ? (Bp + (size_t)r * PP + n0 + bCc)
                                       : (attB + (size_t)(r - C2C) * PP + n0 + bCc);
            cp16(dst, src);
        }
        cp_commit();
    };

    float acc[2][8][4];
#pragma unroll
    for (int mi = 0; mi < 2; mi++)
#pragma unroll
        for (int ni = 0; ni < 8; ni++)
#pragma unroll
            for (int r = 0; r < 4; r++) acc[mi][ni][r] = 0.f;

    const int KT = K / BK;
    issue(0);
    if (KT > 1) issue(1);

    for (int kt = 0; kt < KT; kt++) {
        if (kt + 1 < KT) { asm volatile("cp.async.wait_group 1;\n" ::: "memory"); }
        else             { asm volatile("cp.async.wait_group 0;\n" ::: "memory"); }
        __syncthreads();
        if (kt + 2 < KT) issue(kt + 2);

        const float* As = sm + (kt % 3) * GT_STAGE;
        const float* Bs = As + GT_AW;
        const int k0 = kt * BK;

#pragma unroll
        for (int kk = 0; kk < 4; kk++) {
            const int kb = kk * 8;
            uint32_t a[2][4];
#pragma unroll
            for (int mi = 0; mi < 2; mi++) {
                int m = wm * 32 + mi * 16 + g;
                a[mi][0] = f2tf32(As[m * AS_STRIDE + kb + tig]);
                a[mi][1] = f2tf32(As[(m + 8) * AS_STRIDE + kb + tig]);
                a[mi][2] = f2tf32(As[m * AS_STRIDE + kb + tig + 4]);
                a[mi][3] = f2tf32(As[(m + 8) * AS_STRIDE + kb + tig + 4]);
            }
            uint32_t b[8][2];
            if (!GATE) {
#pragma unroll
                for (int ni = 0; ni < 8; ni++) {
                    int n = wn * 64 + ni * 8 + g;
                    b[ni][0] = f2tf32(Bs[(kb + tig) * GT_BSTR + n]);
                    b[ni][1] = f2tf32(Bs[(kb + tig + 4) * GT_BSTR + n]);
                }
            } else {
                int kr0 = k0 + kb + tig, kr1 = kr0 + 4;
                float cs0 = (kr0 >= C2C) ? cs_s[kr0 - C2C] : 0.f;
                float cs1 = (kr1 >= C2C) ? cs_s[kr1 - C2C] : 0.f;
#pragma unroll
                for (int ni = 0; ni < 8; ni++) {
                    int n = wn * 64 + ni * 8 + g;
                    float s0 = (kr0 < C2C) ? ss_s[n] : cs0;
                    float s1 = (kr1 < C2C) ? ss_s[n] : cs1;
                    b[ni][0] = f2tf32(Bs[(kb + tig) * GT_BSTR + n] * s0);
                    b[ni][1] = f2tf32(Bs[(kb + tig + 4) * GT_BSTR + n] * s1);
                }
            }
#pragma unroll
            for (int mi = 0; mi < 2; mi++)
#pragma unroll
                for (int ni = 0; ni < 8; ni++)
                    mma_tf32(acc[mi][ni], a[mi], b[ni]);
        }
        __syncthreads();
    }

#pragma unroll
    for (int mi = 0; mi < 2; mi++) {
        int row_lo = m0 + wm * 32 + mi * 16 + g;
        int row_hi = row_lo + 8;
        float blo = (row_lo < M) ? bias[row_lo] : 0.f;
        float bhi = (row_hi < M) ? bias[row_hi] : 0.f;
#pragma unroll
        for (int ni = 0; ni < 8; ni++) {
            int col = n0 + wn * 64 + ni * 8 + tig * 2;
            float v0 = acc[mi][ni][0] + blo, v1 = acc[mi][ni][1] + blo;
            float v2 = acc[mi][ni][2] + bhi, v3 = acc[mi][ni][3] + bhi;
            if (ACT == 1) { v0 = fmaxf(v0, 0.f); v1 = fmaxf(v1, 0.f);
                            v2 = fmaxf(v2, 0.f); v3 = fmaxf(v3, 0.f); }
            if (ACT == 2) { v0 = tanhf(v0); v1 = tanhf(v1);
                            v2 = tanhf(v2); v3 = tanhf(v3); }
            if (row_lo < M) *(float2*)(Cp + (size_t)row_lo * N + col) = make_float2(v0, v1);
            if (row_hi < M) *(float2*)(Cp + (size_t)row_hi * N + col) = make_float2(v2, v3);
        }
    }
}

// ---------------- conv-fused GEMM horizontal (cp.async staged) ------------------
__global__ __launch_bounds__(512) void gemm_conv_h(
    const float* __restrict__ A, const float* __restrict__ bias,
    const float* __restrict__ X, size_t sX,
    const float* __restrict__ w7, const float* __restrict__ cb,
    float* __restrict__ Cm, int M, int K, int N, size_t sC)
{
    extern __shared__ float sm[];

    const int bz = blockIdx.z;
    const float* Xp = X + (size_t)bz * sX;
    float*       Cp = Cm + (size_t)bz * sC;

    const int n0 = blockIdx.x * CB_N;
    const int tid  = threadIdx.x;
    const int lane = tid & 31, warp = tid >> 5;
    const int wm = warp & 3, wn = warp >> 2;
    const int g = lane >> 2, tig = lane & 3;

    const int aRow = tid >> 3, aCc = (tid & 7) << 2;
    const int xCh  = tid >> 4, xPx = (tid & 15) << 3;

    auto issue = [&](int kt) {
        const int k0 = kt * BK;
        float* As = sm + (kt % 3) * CH_AW;
        float* Xs = sm + CH_X_OFF + (kt % 3) * CH_XW;
        uint32_t dstA = (uint32_t)__cvta_generic_to_shared(As + aRow * AS_STRIDE + aCc);
        cp16_sz(dstA, A + (size_t)aRow * K + k0 + aCc, (aRow < M) ? 16 : 0);
        const float* src = Xp + (size_t)(k0 + xCh) * PP + n0 + xPx;
        uint32_t dstX = (uint32_t)__cvta_generic_to_shared(Xs + xCh * CH_XSTR + xPx);
        cp16(dstX, src);
        cp16(dstX + 16, src + 4);
        cp_commit();
    };

    auto convpass = [&](int kt) {
        const int k0 = kt * BK;
        const float* Xs = sm + CH_X_OFF + (kt % 3) * CH_XW + xCh * CH_XSTR;
        float*       Bs = sm + CH_B_OFF + (kt & 1) * CH_BW + xCh * CH_BSTR;
        const float* wc = w7 + (size_t)(k0 + xCh) * 7;
        float bb = cb[k0 + xCh];
        float v[14];
#pragma unroll
        for (int t = 0; t < 14; t++) {
            int px = xPx - 3 + t;
            v[t] = (px >= 0 && px < WW) ? Xs[px] : 0.f;
        }
#pragma unroll
        for (int j = 0; j < 8; j++) {
            float s = bb;
#pragma unroll
            for (int t = 0; t < 7; t++) s = fmaf(v[j + t], wc[t], s);
            Bs[xPx + j] = s;
        }
    };

    float acc[4][4];
#pragma unroll
    for (int ni = 0; ni < 4; ni++)
#pragma unroll
        for (int r = 0; r < 4; r++) acc[ni][r] = 0.f;

    const int KT = K / BK;
    issue(0);
    issue(1);

    for (int kt = 0; kt < KT; kt++) {
        if (kt + 1 < KT) { asm volatile("cp.async.wait_group 1;\n" ::: "memory"); }
        else             { asm volatile("cp.async.wait_group 0;\n" ::: "memory"); }
        __syncthreads();
        convpass(kt);
        if (kt + 2 < KT) issue(kt + 2);
        __syncthreads();

        const float* As = sm + (kt % 3) * CH_AW;
        const float* Bs = sm + CH_B_OFF + (kt & 1) * CH_BW;
#pragma unroll
        for (int kk = 0; kk < 4; kk++) {
            const int kb = kk * 8;
            uint32_t a[4];
            {
                int m = wm * 16 + g;
                a[0] = f2tf32(As[m * AS_STRIDE + kb + tig]);
                a[1] = f2tf32(As[(m + 8) * AS_STRIDE + kb + tig]);
                a[2] = f2tf32(As[m * AS_STRIDE + kb + tig + 4]);
                a[3] = f2tf32(As[(m + 8) * AS_STRIDE + kb + tig + 4]);
            }
            uint32_t b[4][2];
#pragma unroll
            for (int ni = 0; ni < 4; ni++) {
                int n = wn * 32 + ni * 8 + g;
                b[ni][0] = f2tf32(Bs[(kb + tig) * CH_BSTR + n]);
                b[ni][1] = f2tf32(Bs[(kb + tig + 4) * CH_BSTR + n]);
            }
#pragma unroll
            for (int ni = 0; ni < 4; ni++)
                mma_tf32(acc[ni], a, b[ni]);
        }
    }

    {
        int row_lo = wm * 16 + g;
        int row_hi = row_lo + 8;
        float blo = (row_lo < M) ? bias[row_lo] : 0.f;
        float bhi = (row_hi < M) ? bias[row_hi] : 0.f;
#pragma unroll
        for (int ni = 0; ni < 4; ni++) {
            int col = n0 + wn * 32 + ni * 8 + tig * 2;
            float v0 = tanhf(acc[ni][0] + blo), v1 = tanhf(acc[ni][1] + blo);
            float v2 = tanhf(acc[ni][2] + bhi), v3 = tanhf(acc[ni][3] + bhi);
            if (row_lo < M) *(float2*)(Cp + (size_t)row_lo * N + col) = make_float2(v0, v1);
            if (row_hi < M) *(float2*)(Cp + (size_t)row_hi * N + col) = make_float2(v2, v3);
        }
    }
}

// ---------------- conv-fused GEMM vertical (register-staged) --------------------
__global__ __launch_bounds__(512) void gemm_conv_v(
    const float* __restrict__ A, const float* __restrict__ bias,
    const float* __restrict__ X, size_t sX,
    const float* __restrict__ w7, const float* __restrict__ cb,
    float* __restrict__ Cm, int M, int K, int N, size_t sC)
{
    extern __shared__ float sm[];
    float* AsB[2] = { sm, sm + CB_STAGE };

    const int bz = blockIdx.z;
    const float* Xp = X + (size_t)bz * sX;
    float*       Cp = Cm + (size_t)bz * sC;

    const int n0 = blockIdx.x * CB_N;
    const int tid  = threadIdx.x;
    const int lane = tid & 31, warp = tid >> 5;
    const int wm = warp & 3, wn = warp >> 2;
    const int g = lane >> 2, tig = lane & 3;

    const int aRow = tid >> 3, aCc = (tid & 7) << 2;
    const int bRow = tid >> 5, bCc = (tid & 31) << 2;

    float4 ra, rb[2];

    auto loadA = [&](int k0) {
        ra = (aRow < M) ? *(const float4*)(A + (size_t)aRow * K + k0 + aCc)
                        : make_float4(0.f, 0.f, 0.f, 0.f);
    };
    auto loadB = [&](int k0) {
#pragma unroll
        for (int i = 0; i < 2; i++) {
            int c = k0 + bRow + i * 16;
            float bb = cb[c];
            const float* wc = w7 + c * 7;
            int h = n0 >> 7;
            const float* xb = Xp + (size_t)c * PP + bCc;
            float4 vt[7];
#pragma unroll
            for (int t = 0; t < 7; t++) {
                int hh = h - 3 + t;
                vt[t] = (hh >= 0 && hh < HH) ? *(const float4*)(xb + hh * WW)
                                             : make_float4(0.f, 0.f, 0.f, 0.f);
            }
            float s0 = bb, s1 = bb, s2 = bb, s3 = bb;
#pragma unroll
            for (int t = 0; t < 7; t++) {
                float wv = wc[t];
                s0 = fmaf(vt[t].x, wv, s0);
                s1 = fmaf(vt[t].y, wv, s1);
                s2 = fmaf(vt[t].z, wv, s2);
                s3 = fmaf(vt[t].w, wv, s3);
            }
            rb[i] = make_float4(s0, s1, s2, s3);
        }
    };
    auto stsAB = [&](int buf) {
        float* As = AsB[buf];
        float* Bs = As + CB_AW;
        *(float4*)&As[aRow * AS_STRIDE + aCc] = ra;
#pragma unroll
        for (int i = 0; i < 2; i++)
            *(float4*)&Bs[(bRow + i * 16) * CB_BSTR + bCc] = rb[i];
    };

    float acc[4][4];
#pragma unroll
    for (int ni = 0; ni < 4; ni++)
#pragma unroll
        for (int r = 0; r < 4; r++) acc[ni][r] = 0.f;

    const int KT = K / BK;
    loadA(0); loadB(0);
    stsAB(0);
    __syncthreads();

    int buf = 0;
    for (int kt = 0;;) {
        const int knext = kt + 1;
        if (knext < KT) { loadA(knext * BK); loadB(knext * BK); }

        const float* As = AsB[buf];
        const float* Bs = As + CB_AW;
#pragma unroll
        for (int kk = 0; kk < 4; kk++) {
            const int kb = kk * 8;
            uint32_t a[4];
            {
                int m = wm * 16 + g;
                a[0] = f2tf32(As[m * AS_STRIDE + kb + tig]);
                a[1] = f2tf32(As[(m + 8) * AS_STRIDE + kb + tig]);
                a[2] = f2tf32(As[m * AS_STRIDE + kb + tig + 4]);
                a[3] = f2tf32(As[(m + 8) * AS_STRIDE + kb + tig + 4]);
            }
            uint32_t b[4][2];
#pragma unroll
            for (int ni = 0; ni < 4; ni++) {
                int n = wn * 32 + ni * 8 + g;
                b[ni][0] = f2tf32(Bs[(kb + tig) * CB_BSTR + n]);
                b[ni][1] = f2tf32(Bs[(kb + tig + 4) * CB_BSTR + n]);
            }
#pragma unroll
            for (int ni = 0; ni < 4; ni++)
                mma_tf32(acc[ni], a, b[ni]);
        }

        if (knext >= KT) break;
        stsAB(buf ^ 1);
        __syncthreads();
        buf ^= 1;
        kt = knext;
    }

    {
        int row_lo = wm * 16 + g;
        int row_hi = row_lo + 8;
        float blo = (row_lo < M) ? bias[row_lo] : 0.f;
        float bhi = (row_hi < M) ? bias[row_hi] : 0.f;
#pragma unroll
        for (int ni = 0; ni < 4; ni++) {
            int col = n0 + wn * 32 + ni * 8 + tig * 2;
            float v0 = tanhf(acc[ni][0] + blo), v1 = tanhf(acc[ni][1] + blo);
            float v2 = tanhf(acc[ni][2] + bhi), v3 = tanhf(acc[ni][3] + bhi);
            if (row_lo < M) *(float2*)(Cp + (size_t)row_lo * N + col) = make_float2(v0, v1);
            if (row_hi < M) *(float2*)(Cp + (size_t)row_hi * N + col) = make_float2(v2, v3);
        }
    }
}

// ---------------- FSA horizontal, 4 outputs/thread -----------------------------
__global__ void fsa_h4(const float* __restrict__ x, size_t sX,
                       const float* __restrict__ kern, float* __restrict__ out)
{
    int idx = blockIdx.x * 256 + threadIdx.x;
    if (idx >= NB * C2C * HH * (WW / 4)) return;
    int w4 = (idx & 31) << 2;
    int row = idx >> 5;
    int h = row % HH, c = (row / HH) % C2C, b = row / (HH * C2C);
    const float* xr = x + (size_t)b * sX + (size_t)c * PP + h * WW;
    float v[10];
    load_win10(xr, w4, v);
    const float* kb_ = kern + ((size_t)b * GKC + (size_t)(c >> 4) * 5) * PP + h * WW + w4;
    float4 k0 = *(const float4*)(kb_);
    float4 k1 = *(const float4*)(kb_ + PP);
    float4 k2 = *(const float4*)(kb_ + 2 * PP);
    float4 k3 = *(const float4*)(kb_ + 3 * PP);
    float4 k4 = *(const float4*)(kb_ + 4 * PP);
    float K0[4] = {k0.x, k0.y, k0.z, k0.w};
    float K1[4] = {k1.x, k1.y, k1.z, k1.w};
    float K2[4] = {k2.x, k2.y, k2.z, k2.w};
    float K3[4] = {k3.x, k3.y, k3.z, k3.w};
    float K4[4] = {k4.x, k4.y, k4.z, k4.w};
    float o[4];
#pragma unroll
    for (int i = 0; i < 4; i++) {
        float t0 = (v[i] + v[i + 1]) * 0.5f;
        float t4 = (v[i + 5] + v[i + 6]) * 0.5f;
        float s = t0 * K0[i];
        s = fmaf(v[i + 2], K1[i], s);
        s = fmaf(v[i + 3], K2[i], s);
        s = fmaf(v[i + 4], K3[i], s);
        s = fmaf(t4, K4[i], s);
        o[i] = s;
    }
    *(float4*)(out + ((size_t)b * C2C + c) * PP + h * WW + w4) = make_float4(o[0], o[1], o[2], o[3]);
}

// ---------------- FSA vertical, 4 outputs/thread --------------------------------
__global__ void fsa_v4(const float* __restrict__ x, size_t sX,
                       const float* __restrict__ kern, float* __restrict__ out)
{
    int idx = blockIdx.x * 256 + threadIdx.x;
    if (idx >= NB * C2C * (HH / 4) * WW) return;
    int w = idx % WW;
    int h4 = ((idx / WW) & 31) << 2;
    int c = (idx / (WW * 32)) % C2C;
    int b = idx / (WW * 32 * C2C);
    const float* xc = x + (size_t)b * sX + (size_t)c * PP;
    float v[10];
#pragma unroll
    for (int t = 0; t < 10; t++) {
        int hi = h4 - 3 + t;
        v[t] = (hi >= 0 && hi < HH) ? xc[hi * WW + w] : 0.f;
    }
    const float* kb_ = kern + ((size_t)b * GKC + (size_t)(c >> 4) * 5) * PP + h4 * WW + w;
    float* ob = out + ((size_t)b * C2C + c) * PP + h4 * WW + w;
#pragma unroll
    for (int i = 0; i < 4; i++) {
        float t0 = (v[i] + v[i + 1]) * 0.5f;
        float t4 = (v[i + 5] + v[i + 6]) * 0.5f;
        float s = t0 * kb_[i * WW];
        s = fmaf(v[i + 2], kb_[PP + i * WW], s);
        s = fmaf(v[i + 3], kb_[2 * PP + i * WW], s);
        s = fmaf(v[i + 4], kb_[3 * PP + i * WW], s);
        s = fmaf(t4, kb_[4 * PP + i * WW], s);
        ob[i * WW] = s;
    }
}

// ---------------- reductions / gating -------------------------------------------
__global__ void reduce_mean_p(const float* __restrict__ x, float* __restrict__ out)
{
    int bc = blockIdx.x;
    const float* xr = x + (size_t)bc * PP;
    float s = 0.f;
    for (int i = threadIdx.x; i < PP; i += 256) s += xr[i];
    __shared__ float sm[256];
    sm[threadIdx.x] = s; __syncthreads();
    for (int st = 128; st > 0; st >>= 1) {
        if (threadIdx.x < st) sm[threadIdx.x] += sm[threadIdx.x + st];
        __syncthreads();
    }
    if (threadIdx.x == 0) out[bc] = sm[0] * (1.f / PP);
}

__global__ void ssig_xcmean(const float* __restrict__ xconv,
                            const float* __restrict__ atmean,
                            float* __restrict__ ssig, float* __restrict__ xcm)
{
    int b = blockIdx.y;
    int p = blockIdx.x * 256 + threadIdx.x;
    __shared__ float am[C2C];
    if (threadIdx.x < C2C) am[threadIdx.x] = atmean[b * C2C + threadIdx.x];
    __syncthreads();
    const float* xr = xconv + (size_t)b * C2C * PP + p;
    float s = 0.f, m = 0.f;
#pragma unroll 8
    for (int c = 0; c < C2C; c++) {
        float v = xr[(size_t)c * PP];
        s = fmaf(am[c], v, s);
        m += v;
    }
    s *= (1.f / C2C);
    ssig[b * PP + p] = 1.f / (1.f + expf(-s));
    xcm[b * PP + p] = m * (1.f / C2C);
}

__global__ void csig_kernel(const float* __restrict__ attn,
                            const float* __restrict__ xcmean,
                            float* __restrict__ out)
{
    int bc = blockIdx.x;
    int b = bc / C2C;
    const float* ar = attn + (size_t)bc * PP;
    const float* xm = xcmean + (size_t)b * PP;
    float s = 0.f;
    for (int i = threadIdx.x; i < PP; i += 256) s = fmaf(ar[i], xm[i], s);
    __shared__ float sm[256];
    sm[threadIdx.x] = s; __syncthreads();
    for (int st = 128; st > 0; st >>= 1) {
        if (threadIdx.x < st) sm[threadIdx.x] += sm[threadIdx.x + st];
        __syncthreads();
    }
    if (threadIdx.x == 0) {
        float v = sm[0] * (1.f / PP);
        out[bc] = 1.f / (1.f + expf(-v));
    }
}

// ---------------- host orchestration --------------------------------------------
extern "C" void kernel_launch(void* const* d_in, const int* in_sizes, int n_in,
                              void* d_out, int out_size)
{
    const float* x         = (const float*)d_in[0];
    const float* proj_in_w = (const float*)d_in[1];
    const float* proj_in_b = (const float*)d_in[2];
    const float* hk_dw_w   = (const float*)d_in[3];
    const float* hk_dw_b   = (const float*)d_in[4];
    const float* hk_pw_w   = (const float*)d_in[5];
    const float* hk_pw_b   = (const float*)d_in[6];
    const float* vk_dw_w   = (const float*)d_in[7];
    const float* vk_dw_b   = (const float*)d_in[8];
    const float* vk_pw_w   = (const float*)d_in[9];
    const float* vk_pw_b   = (const float*)d_in[10];
    const float* cb_w1     = (const float*)d_in[11];
    const float* cb_b1     = (const float*)d_in[12];
    const float* cb_w2     = (const float*)d_in[13];
    const float* cb_b2     = (const float*)d_in[14];
    const float* proj_out_w= (const float*)d_in[15];
    const float* proj_out_b= (const float*)d_in[16];
    float* out = (float*)d_out;

    static int smem_set = 0;
    if (!smem_set) {
        cudaFuncSetAttribute(gemm_tc256<0,0>, cudaFuncAttributeMaxDynamicSharedMemorySize, GT_BYTES);
        cudaFuncSetAttribute(gemm_tc256<1,0>, cudaFuncAttributeMaxDynamicSharedMemorySize, GT_BYTES);
        cudaFuncSetAttribute(gemm_tc256<0,1>, cudaFuncAttributeMaxDynamicSharedMemorySize, GT_BYTES);
        cudaFuncSetAttribute(gemm_conv_h,     cudaFuncAttributeMaxDynamicSharedMemorySize, CHSMEM_BYTES);
        cudaFuncSetAttribute(gemm_conv_v,     cudaFuncAttributeMaxDynamicSharedMemorySize, CBSMEM_BYTES);
        smem_set = 1;
    }

    float *p_h, *p_mid, *p_xconv, *p_k, *p_attnh, *p_attn;
    float *p_atmean, *p_xcmean, *p_ssig, *p_csig;
    cudaGetSymbolAddress((void**)&p_h,      g_h);
    cudaGetSymbolAddress((void**)&p_mid,    g_mid);
    cudaGetSymbolAddress((void**)&p_xconv,  g_xconv);
    cudaGetSymbolAddress((void**)&p_k,      g_k);
    cudaGetSymbolAddress((void**)&p_attnh,  g_attnh);
    cudaGetSymbolAddress((void**)&p_attn,   g_attn);
    cudaGetSymbolAddress((void**)&p_atmean, g_atmean);
    cudaGetSymbolAddress((void**)&p_xcmean, g_xcmean);
    cudaGetSymbolAddress((void**)&p_ssig,   g_ssig);
    cudaGetSymbolAddress((void**)&p_csig,   g_csig);

    const int N = PP;
    const int eb4 = (NB * C2C * PP / 4) / 256;

    // 1) proj_in (M=256,K=256): 128x128 tiles, 2 CTAs/SM
    gemm_tc256<0,0><<<dim3(N/128, 2, NB), 256, GT_BYTES>>>(proj_in_w, proj_in_b, x, p_h,
        256, 256, N, (size_t)256*PP, (size_t)256*PP, nullptr, nullptr, nullptr);
    // 2) cb hidden = relu (M=64,K=128)
    gemm_tc256<1,0><<<dim3(N/128, 1, NB), 256, GT_BYTES>>>(cb_w1, cb_b1, p_h, p_mid,
        64, 128, N, (size_t)256*PP, (size_t)64*PP, nullptr, nullptr, nullptr);
    // 3) x_conv (M=128,K=64)
    gemm_tc256<0,0><<<dim3(N/128, 1, NB), 256, GT_BYTES>>>(cb_w2, cb_b2, p_mid, p_xconv,
        128, 64, N, (size_t)64*PP, (size_t)C2C*PP, nullptr, nullptr, nullptr);
    // 4+5) kh = tanh(hk_pw · dwconv_h(x2))
    gemm_conv_h<<<dim3(N/CB_N, 1, NB), 512, CHSMEM_BYTES>>>(hk_pw_w, hk_pw_b,
        p_h + (size_t)C2C*PP, (size_t)256*PP, hk_dw_w, hk_dw_b, p_k,
        GKC, 128, N, (size_t)GKC*PP);
    // 6) attn_h
    fsa_h4<<<eb4, 256>>>(p_h + (size_t)C2C*PP, (size_t)256*PP, p_k, p_attnh);
    // 7+8) kv = tanh(vk_pw · dwconv_v(attn_h))
    gemm_conv_v<<<dim3(N/CB_N, 1, NB), 512, CBSMEM_BYTES>>>(vk_pw_w, vk_pw_b,
        p_attnh, (size_t)C2C*PP, vk_dw_w, vk_dw_b, p_k,
        GKC, 128, N, (size_t)GKC*PP);
    // 9) attn
    fsa_v4<<<eb4, 256>>>(p_attnh, (size_t)C2C*PP, p_k, p_attn);
    // 10) at_mean
    reduce_mean_p<<<NB*C2C, 256>>>(p_attn, p_atmean);
    // 11) fused ssig + xcmean
    ssig_xcmean<<<dim3(PP/256, NB), 256>>>(p_xconv, p_atmean, p_ssig, p_xcmean);
    // 12) c_sig
    csig_kernel<<<NB*C2C, 256>>>(p_attn, p_xcmean, p_csig);
    // 13) proj_out with fused gating/concat (M=256,K=256)
    gemm_tc256<0,1><<<dim3(N/128, 2, NB), 256, GT_BYTES>>>(proj_out_w, proj_out_b, p_xconv, out,
        256, 256, N, (size_t)C2C*PP, (size_t)256*PP, p_attn, p_ssig, p_csig);
}